// round 15
// baseline (speedup 1.0000x reference)
#include <cuda_runtime.h>
#include <math.h>

typedef unsigned long long ull;

// B=32 C=512 S=512 T=128 V=512 E=128 EH=256 DH=256
// Attention softmax is invariant to the h2 term -> ctx constant over steps.
// Hidden states packed: element (j, lane) at (j>>1)*64 + lane*2 + (j&1) so a
// (h_j, h_{j+1}) pair for one lane is one 8-byte word -> feeds fma.rn.f32x2.
// GEMM B tiles stored as duplicated pairs (v,v) in smem -> f32x2 operands load
// directly, no splat MOVs in the inner loop.

__device__ __align__(128) float d_giT[2][512][768 * 32];
__device__ __align__(128) float d_encT[512][512 * 32];
__device__ __align__(128) float d_hEnc[2][2][8192];
__device__ __align__(128) float d_score[512 * 32];
__device__ __align__(128) float d_w[512 * 32];
__device__ __align__(128) float d_ctx[512 * 32];
__device__ __align__(128) float d_vg[512 * 768];
__device__ __align__(128) float d_cg[768 * 32];
__device__ __align__(128) float d_gi0[128][768 * 32];
__device__ __align__(128) float d_h1all[128][8192];
__device__ __align__(128) float d_h1z[8192];
__device__ __align__(128) float d_h2p[2][8192];
__device__ __align__(128) float d_h2all[128][8192];
__device__ __align__(128) unsigned g_cnt[4 * 32];

__device__ __forceinline__ float sigm(float x) { return 1.f / (1.f + expf(-x)); }
__device__ __forceinline__ void f2(ull& d, ull a, ull b) {
    asm("fma.rn.f32x2 %0,%1,%2,%0;" : "+l"(d) : "l"(a), "l"(b));
}
__device__ __forceinline__ void upk(ull v, float& x, float& y) {
    asm("mov.b64 {%0,%1},%2;" : "=f"(x), "=f"(y) : "l"(v));
}
__device__ __forceinline__ float fsum(ull v) { float x, y; upk(v, x, y); return x + y; }

__device__ __forceinline__ void g_arrive(int id) {
    asm volatile("red.release.gpu.global.add.u32 [%0],%1;"
                 :: "l"(&g_cnt[id * 32]), "r"(1u) : "memory");
}
__device__ __forceinline__ void g_waitge(int id, unsigned target) {
    unsigned v;
    do {
        asm volatile("ld.acquire.gpu.global.u32 %0,[%1];"
                     : "=r"(v) : "l"(&g_cnt[id * 32]) : "memory");
    } while (v < target);
}

__device__ __forceinline__ void cp16(unsigned dst, const float* src) {
    asm volatile("cp.async.cg.shared.global [%0],[%1],16;"
                 :: "r"(dst), "l"(src) : "memory");
}

// 6-gate dot over one quarter (64 j) of a packed h vector.
__device__ __forceinline__ void gru_dots(const float* hb, const float* wg, ull* acc) {
#pragma unroll
    for (int it = 0; it < 8; it++) {
        ull h0 = *(const ull*)(hb + (it * 4 + 0) * 64);
        ull h1 = *(const ull*)(hb + (it * 4 + 1) * 64);
        ull h2 = *(const ull*)(hb + (it * 4 + 2) * 64);
        ull h3 = *(const ull*)(hb + (it * 4 + 3) * 64);
#pragma unroll
        for (int g = 0; g < 6; g++) {
            ulonglong2 xa = *(const ulonglong2*)(wg + g * 256 + it * 8);
            ulonglong2 xb = *(const ulonglong2*)(wg + g * 256 + it * 8 + 4);
            f2(acc[g], h0, xa.x); f2(acc[g], h1, xa.y);
            f2(acc[g], h2, xb.x); f2(acc[g], h3, xb.y);
        }
    }
}

__global__ void init_kernel() {
    int i = blockIdx.x * 256 + threadIdx.x;
    if (i < 32768) ((float*)d_hEnc)[i] = 0.f;
    if (i < 8192) d_h1z[i] = 0.f;
    if (i < 16384) ((float*)d_h2p)[i] = 0.f;
    if (i < 128) g_cnt[i] = 0u;
}

// ---- vocab part of dec0 input gates ----------------------------------------
__global__ void __launch_bounds__(256) vg_k(const float* __restrict__ emb,
                                            const float* __restrict__ W0i) {
    __shared__ float e[128];
    int v = blockIdx.x;
    if (threadIdx.x < 128) e[threadIdx.x] = __ldg(emb + v * 128 + threadIdx.x);
    __syncthreads();
    for (int g = threadIdx.x; g < 768; g += 256) {
        const float4* w = (const float4*)(W0i + (size_t)g * 640);
        float acc = 0.f;
#pragma unroll 8
        for (int k = 0; k < 32; k++) {
            float4 wv = __ldg(w + k);
            acc = fmaf(wv.x, e[4 * k], acc);
            acc = fmaf(wv.y, e[4 * k + 1], acc);
            acc = fmaf(wv.z, e[4 * k + 2], acc);
            acc = fmaf(wv.w, e[4 * k + 3], acc);
        }
        d_vg[v * 768 + g] = acc;
    }
}

// ---- encoder input GEMM: M=16384 K=512 N=1536, dup-B (no splats) -----------
__global__ void __launch_bounds__(256) enc_gi_gemm(
    const float* __restrict__ src, const float* __restrict__ Wf,
    const float* __restrict__ Wb, const float* __restrict__ bf,
    const float* __restrict__ bb) {
    __shared__ __align__(16) float As[2][16][128];
    __shared__ __align__(16) float Bs[2][16][256];   // duplicated pairs
    int n0 = blockIdx.x << 7, m0 = blockIdx.y << 7;
    int bIdx = m0 >> 9, s0 = m0 & 511;
    int tid = threadIdx.x, tx = tid & 31, ty = tid >> 5;
    const float* aBase = src + (size_t)bIdx * 262144 + s0;
    int nl = tid & 127, kg = tid >> 7;
    int nld = n0 + nl;
    const float* Wr = (nld < 768) ? (Wf + (size_t)nld * 512)
                                  : (Wb + (size_t)(nld - 768) * 512);
    int kl0 = tid >> 5, mo0 = (tid & 31) << 2;
    int kl1 = (tid + 256) >> 5;

    ull acc2[8][4];
#pragma unroll
    for (int i = 0; i < 8; i++)
#pragma unroll
        for (int j = 0; j < 4; j++) acc2[i][j] = 0ull;

    cp16((unsigned)__cvta_generic_to_shared(&As[0][kl0][mo0]), aBase + kl0 * 512 + mo0);
    cp16((unsigned)__cvta_generic_to_shared(&As[0][kl1][mo0]), aBase + kl1 * 512 + mo0);
    asm volatile("cp.async.commit_group;" ::: "memory");
    {
        float4 bv0 = __ldg((const float4*)(Wr + (kg << 3)));
        float4 bv1 = __ldg((const float4*)(Wr + (kg << 3) + 4));
        int kb = kg << 3, n2 = nl << 1;
        *(float2*)&Bs[0][kb + 0][n2] = make_float2(bv0.x, bv0.x);
        *(float2*)&Bs[0][kb + 1][n2] = make_float2(bv0.y, bv0.y);
        *(float2*)&Bs[0][kb + 2][n2] = make_float2(bv0.z, bv0.z);
        *(float2*)&Bs[0][kb + 3][n2] = make_float2(bv0.w, bv0.w);
        *(float2*)&Bs[0][kb + 4][n2] = make_float2(bv1.x, bv1.x);
        *(float2*)&Bs[0][kb + 5][n2] = make_float2(bv1.y, bv1.y);
        *(float2*)&Bs[0][kb + 6][n2] = make_float2(bv1.z, bv1.z);
        *(float2*)&Bs[0][kb + 7][n2] = make_float2(bv1.w, bv1.w);
    }
    asm volatile("cp.async.wait_group 0;" ::: "memory");
    __syncthreads();

    for (int t = 0; t < 32; t++) {
        int pb = t & 1;
        float4 bv0, bv1;
        if (t < 31) {
            int k0n = (t + 1) << 4;
            cp16((unsigned)__cvta_generic_to_shared(&As[pb ^ 1][kl0][mo0]),
                 aBase + (k0n + kl0) * 512 + mo0);
            cp16((unsigned)__cvta_generic_to_shared(&As[pb ^ 1][kl1][mo0]),
                 aBase + (k0n + kl1) * 512 + mo0);
            asm volatile("cp.async.commit_group;" ::: "memory");
            bv0 = __ldg((const float4*)(Wr + k0n + (kg << 3)));
            bv1 = __ldg((const float4*)(Wr + k0n + (kg << 3) + 4));
        }
#pragma unroll
        for (int k = 0; k < 16; k++) {
            ulonglong2 qa0 = *(const ulonglong2*)&As[pb][k][(ty << 4) + 0];
            ulonglong2 qa1 = *(const ulonglong2*)&As[pb][k][(ty << 4) + 4];
            ulonglong2 qa2 = *(const ulonglong2*)&As[pb][k][(ty << 4) + 8];
            ulonglong2 qa3 = *(const ulonglong2*)&As[pb][k][(ty << 4) + 12];
            ulonglong2 qb0 = *(const ulonglong2*)&Bs[pb][k][tx << 3];
            ulonglong2 qb1 = *(const ulonglong2*)&Bs[pb][k][(tx << 3) + 4];
            ull bsp[4] = {qb0.x, qb0.y, qb1.x, qb1.y};
            ull am[8] = {qa0.x, qa0.y, qa1.x, qa1.y, qa2.x, qa2.y, qa3.x, qa3.y};
#pragma unroll
            for (int mp = 0; mp < 8; mp++) {
                f2(acc2[mp][0], am[mp], bsp[0]);
                f2(acc2[mp][1], am[mp], bsp[1]);
                f2(acc2[mp][2], am[mp], bsp[2]);
                f2(acc2[mp][3], am[mp], bsp[3]);
            }
        }
        if (t < 31) {
            int kb = kg << 3, nb = pb ^ 1, n2 = nl << 1;
            *(float2*)&Bs[nb][kb + 0][n2] = make_float2(bv0.x, bv0.x);
            *(float2*)&Bs[nb][kb + 1][n2] = make_float2(bv0.y, bv0.y);
            *(float2*)&Bs[nb][kb + 2][n2] = make_float2(bv0.z, bv0.z);
            *(float2*)&Bs[nb][kb + 3][n2] = make_float2(bv0.w, bv0.w);
            *(float2*)&Bs[nb][kb + 4][n2] = make_float2(bv1.x, bv1.x);
            *(float2*)&Bs[nb][kb + 5][n2] = make_float2(bv1.y, bv1.y);
            *(float2*)&Bs[nb][kb + 6][n2] = make_float2(bv1.z, bv1.z);
            *(float2*)&Bs[nb][kb + 7][n2] = make_float2(bv1.w, bv1.w);
            asm volatile("cp.async.wait_group 0;" ::: "memory");
        }
        __syncthreads();
    }

#pragma unroll
    for (int n = 0; n < 4; n++) {
        int nn = n0 + (tx << 2) + n;
        int dA = nn >= 768;
        int row = nn - dA * 768;
        float bias = dA ? __ldg(bb + row) : __ldg(bf + row);
#pragma unroll
        for (int mp = 0; mp < 8; mp++) {
            float lo, hi;
            upk(acc2[mp][n], lo, hi);
            int s = s0 + (ty << 4) + (mp << 1);
            d_giT[dA][s][row * 32 + bIdx] = lo + bias;
            d_giT[dA][s + 1][row * 32 + bIdx] = hi + bias;
        }
    }
}

// ---- encoder recurrence: 128 blocks (64/dir) x 256 thr ---------------------
// per-warp polling: wait moved to top of step, lane0 of each warp polls.
__global__ void __launch_bounds__(256) enc_rnn(
    const float* __restrict__ Whh_f, const float* __restrict__ bhh_f,
    const float* __restrict__ Whh_b, const float* __restrict__ bhh_b) {
    int dir = blockIdx.x >> 6, lb = blockIdx.x & 63;
    int u0 = lb * 4;
    const float* Whh = dir ? Whh_b : Whh_f;
    const float* bhh = dir ? bhh_b : bhh_f;
    __shared__ __align__(16) float Ws[12][256];
    __shared__ __align__(16) float Hs[8192];
    __shared__ float parts[4][3][4][32];
    int tid = threadIdx.x;
    for (int i = tid; i < 3072; i += 256) {
        int r = i >> 8, j = i & 255;
        Ws[r][j] = __ldg(Whh + (size_t)((r % 3) * 256 + u0 + r / 3) * 256 + j);
    }
    int w = tid >> 5, lane = tid & 31;
    int jq = w >> 1, uh = w & 1;
    int ue = u0 + (w & 3);
    float br = __ldg(bhh + ue), bz = __ldg(bhh + 256 + ue), bn = __ldg(bhh + 512 + ue);
    int pidx = (ue >> 1) * 64 + (lane << 1) + (ue & 1);
    const float* wg = Ws[uh * 6] + (jq << 6);
    int ua = uh * 2, ub = uh * 2 + 1;

    float giR = 0.f, giZ = 0.f, giN = 0.f;
    if (w < 4) {
        int sa0 = dir ? 511 : 0;
        giR = d_giT[dir][sa0][ue * 32 + lane];
        giZ = d_giT[dir][sa0][(256 + ue) * 32 + lane];
        giN = d_giT[dir][sa0][(512 + ue) * 32 + lane];
    }
    __syncthreads();

    for (int s = 0; s < 512; s++) {
        if (s && lane == 0) g_waitge(dir, 64u * s);   // per-warp poll
        __syncwarp();
        int par = s & 1;
        {
            const float4* srcp = (const float4*)d_hEnc[dir][par];
            float4* dst = (float4*)Hs;
            for (int i = tid; i < 2048; i += 256) dst[i] = __ldcg(srcp + i);
        }
        __syncthreads();
        ull acc[6] = {0, 0, 0, 0, 0, 0};
        gru_dots(Hs + (jq << 11) + (lane << 1), wg, acc);
#pragma unroll
        for (int g = 0; g < 3; g++) {
            parts[ua][g][jq][lane] = fsum(acc[g]);
            parts[ub][g][jq][lane] = fsum(acc[g + 3]);
        }
        __syncthreads();
        float hN = 0.f;
        int sa = dir ? (511 - s) : s;
        if (w < 4) {
            float gR = parts[w][0][0][lane] + parts[w][0][1][lane] +
                       parts[w][0][2][lane] + parts[w][0][3][lane];
            float gZ = parts[w][1][0][lane] + parts[w][1][1][lane] +
                       parts[w][1][2][lane] + parts[w][1][3][lane];
            float gN = parts[w][2][0][lane] + parts[w][2][1][lane] +
                       parts[w][2][2][lane] + parts[w][2][3][lane];
            float r = sigm(giR + gR + br);
            float z = sigm(giZ + gZ + bz);
            float nn = tanhf(giN + r * (gN + bn));
            hN = (1.f - z) * nn + z * Hs[pidx];
            __stcg(&d_hEnc[dir][par ^ 1][pidx], hN);
        }
        __syncthreads();                       // hN stores ordered before arrive
        if (tid == 0) g_arrive(dir);
        if (w < 4) {                           // off the inter-block critical path
            d_encT[sa][(dir * 256 + ue) * 32 + lane] = hN;
            if (s < 511) {
                int sn = dir ? (510 - s) : (s + 1);
                giR = d_giT[dir][sn][ue * 32 + lane];
                giZ = d_giT[dir][sn][(256 + ue) * 32 + lane];
                giN = d_giT[dir][sn][(512 + ue) * 32 + lane];
            }
        }
    }
}

// ---- attention (step-invariant) ----
__global__ void __launch_bounds__(256) att_score(const float* __restrict__ attW) {
    int s = blockIdx.x, q = threadIdx.x >> 5, b = threadIdx.x & 31;
    float p = 0.f;
    for (int d = q * 64; d < q * 64 + 64; d++)
        p = fmaf(d_encT[s][d * 32 + b], __ldg(attW + d), p);
    __shared__ float sm[8][32];
    sm[q][b] = p;
    __syncthreads();
    if (threadIdx.x < 32) {
        float v = 0.f;
#pragma unroll
        for (int i = 0; i < 8; i++) v += sm[i][threadIdx.x];
        d_score[s * 32 + threadIdx.x] = v;
    }
}

__global__ void __launch_bounds__(256) softmax_k() {
    int b = blockIdx.x, tid = threadIdx.x;
    float x1 = d_score[tid * 32 + b], x2 = d_score[(tid + 256) * 32 + b];
    __shared__ float sm[256];
    sm[tid] = fmaxf(x1, x2);
    __syncthreads();
    for (int o = 128; o > 0; o >>= 1) {
        if (tid < o) sm[tid] = fmaxf(sm[tid], sm[tid + o]);
        __syncthreads();
    }
    float M = sm[0];
    __syncthreads();
    float e1 = expf(x1 - M), e2 = expf(x2 - M);
    sm[tid] = e1 + e2;
    __syncthreads();
    for (int o = 128; o > 0; o >>= 1) {
        if (tid < o) sm[tid] += sm[tid + o];
        __syncthreads();
    }
    d_w[tid * 32 + b] = e1 / sm[0];
    d_w[(tid + 256) * 32 + b] = e2 / sm[0];
}

__global__ void __launch_bounds__(256) ctx_k() {
    int d = blockIdx.x, q = threadIdx.x >> 5, b = threadIdx.x & 31;
    float p = 0.f;
    for (int s = q * 64; s < q * 64 + 64; s++)
        p = fmaf(d_w[s * 32 + b], d_encT[s][d * 32 + b], p);
    __shared__ float sm[8][32];
    sm[q][b] = p;
    __syncthreads();
    if (threadIdx.x < 32) {
        float v = 0.f;
#pragma unroll
        for (int i = 0; i < 8; i++) v += sm[i][threadIdx.x];
        d_ctx[d * 32 + threadIdx.x] = v;
    }
}

__global__ void __launch_bounds__(256) cg_k(const float* __restrict__ W0i,
                                            const float* __restrict__ b0i) {
    int g = blockIdx.x, q = threadIdx.x >> 5, b = threadIdx.x & 31;
    const float* wrow = W0i + (size_t)g * 640 + 128;
    float p = 0.f;
    for (int d = q * 64; d < q * 64 + 64; d++)
        p = fmaf(d_ctx[d * 32 + b], __ldg(wrow + d), p);
    __shared__ float sm[8][32];
    sm[q][b] = p;
    __syncthreads();
    if (threadIdx.x < 32) {
        float v = __ldg(b0i + g);
#pragma unroll
        for (int i = 0; i < 8; i++) v += sm[i][threadIdx.x];
        d_cg[g * 32 + threadIdx.x] = v;
    }
}

__global__ void __launch_bounds__(256) gi0_k(const int* __restrict__ target) {
    int i = blockIdx.x * 256 + threadIdx.x;
    int t = i / 24576, rem = i - t * 24576;
    int g = rem >> 5, b = rem & 31;
    int tok = __ldg(target + b * 128 + t);
    d_gi0[t][g * 32 + b] = d_vg[tok * 768 + g] + d_cg[g * 32 + b];
}

// ---- decoder: blocks 0-63 = GRU0 chain, 64-127 = GRU1 chain ----------------
__global__ void __launch_bounds__(256) dec_rnn(
    const float* __restrict__ W0h, const float* __restrict__ b0h,
    const float* __restrict__ W1i, const float* __restrict__ b1i,
    const float* __restrict__ W1h, const float* __restrict__ b1h) {
    __shared__ __align__(16) float Wsm[24][256];
    __shared__ __align__(16) float Hs[8192];
    __shared__ __align__(16) float Hs2[8192];
    __shared__ float parts[4][3][4][32];
    int tid = threadIdx.x, w = tid >> 5, lane = tid & 31;

    if (blockIdx.x < 64) {   // ---------------- GRU0 chain -------------------
        int u0 = blockIdx.x * 4;
        for (int i = tid; i < 3072; i += 256) {
            int r = i >> 8, j = i & 255;
            Wsm[r][j] = __ldg(W0h + (size_t)((r % 3) * 256 + u0 + r / 3) * 256 + j);
        }
        int jq = w >> 1, uh = w & 1;
        int ue = u0 + (w & 3);
        float br = __ldg(b0h + ue), bz = __ldg(b0h + 256 + ue), bn = __ldg(b0h + 512 + ue);
        int pidx = (ue >> 1) * 64 + (lane << 1) + (ue & 1);
        const float* wg = Wsm[uh * 6] + (jq << 6);
        int ua = uh * 2, ub = uh * 2 + 1;
        float giR = 0.f, giZ = 0.f, giN = 0.f;
        if (w < 4) {
            giR = d_gi0[0][ue * 32 + lane];
            giZ = d_gi0[0][(256 + ue) * 32 + lane];
            giN = d_gi0[0][(512 + ue) * 32 + lane];
        }
        __syncthreads();
        for (int t = 0; t < 128; t++) {
            if (t && lane == 0) g_waitge(2, 64u * t);   // per-warp poll
            __syncwarp();
            const float4* srcp = (const float4*)((t == 0) ? d_h1z : d_h1all[t - 1]);
            float4* dst = (float4*)Hs;
            for (int i = tid; i < 2048; i += 256) dst[i] = __ldcg(srcp + i);
            __syncthreads();
            ull acc[6] = {0, 0, 0, 0, 0, 0};
            gru_dots(Hs + (jq << 11) + (lane << 1), wg, acc);
#pragma unroll
            for (int g = 0; g < 3; g++) {
                parts[ua][g][jq][lane] = fsum(acc[g]);
                parts[ub][g][jq][lane] = fsum(acc[g + 3]);
            }
            __syncthreads();
            if (w < 4) {
                float gR = parts[w][0][0][lane] + parts[w][0][1][lane] +
                           parts[w][0][2][lane] + parts[w][0][3][lane] + br;
                float gZ = parts[w][1][0][lane] + parts[w][1][1][lane] +
                           parts[w][1][2][lane] + parts[w][1][3][lane] + bz;
                float gN = parts[w][2][0][lane] + parts[w][2][1][lane] +
                           parts[w][2][2][lane] + parts[w][2][3][lane] + bn;
                float r = sigm(giR + gR);
                float z = sigm(giZ + gZ);
                float nn = tanhf(giN + r * gN);
                float hN = (1.f - z) * nn + z * Hs[pidx];
                __stcg(&d_h1all[t][pidx], hN);
            }
            __syncthreads();
            if (tid == 0) g_arrive(2);
            if (w < 4 && t < 127) {
                giR = d_gi0[t + 1][ue * 32 + lane];
                giZ = d_gi0[t + 1][(256 + ue) * 32 + lane];
                giN = d_gi0[t + 1][(512 + ue) * 32 + lane];
            }
        }
    } else {                 // ---------------- GRU1 chain -------------------
        int u0 = (blockIdx.x - 64) * 4;
        for (int i = tid; i < 3072; i += 256) {
            int r = i >> 8, j = i & 255;
            Wsm[r][j] = __ldg(W1i + (size_t)((r % 3) * 256 + u0 + r / 3) * 256 + j);
            Wsm[12 + r][j] = __ldg(W1h + (size_t)((r % 3) * 256 + u0 + r / 3) * 256 + j);
        }
        int mt = w >> 2, jh = (w >> 1) & 1, uh = w & 1;
        int ue = u0 + (w & 3);
        float biR = __ldg(b1i + ue), biZ = __ldg(b1i + 256 + ue), biN = __ldg(b1i + 512 + ue);
        float bhR = __ldg(b1h + ue), bhZ = __ldg(b1h + 256 + ue), bhN = __ldg(b1h + 512 + ue);
        int pidx = (ue >> 1) * 64 + (lane << 1) + (ue & 1);
        int rb = mt * 12 + uh * 6;
        const float* w0 = Wsm[rb + 0] + (jh << 7);
        const float* w1 = Wsm[rb + 1] + (jh << 7);
        const float* w2 = Wsm[rb + 2] + (jh << 7);
        const float* w3 = Wsm[rb + 3] + (jh << 7);
        const float* w4 = Wsm[rb + 4] + (jh << 7);
        const float* w5 = Wsm[rb + 5] + (jh << 7);
        __syncthreads();
        for (int t = 0; t < 128; t++) {
            int par = t & 1;
            {
                const float4* srcp = (const float4*)d_h2p[par];
                float4* dst = (float4*)Hs2;
                for (int i = tid; i < 2048; i += 256) dst[i] = __ldcg(srcp + i);
            }
            __syncthreads();
            if (mt == 0) {
                if (tid == 0) g_waitge(2, 64u * (t + 1));
                asm volatile("bar.sync 1,128;" ::: "memory");
                const float4* srcp = (const float4*)d_h1all[t];
                float4* dst = (float4*)Hs;
                for (int i = tid; i < 2048; i += 128) dst[i] = __ldcg(srcp + i);
                asm volatile("bar.sync 1,128;" ::: "memory");
            }
            ull aA = 0, aB = 0, aC = 0, aD = 0, aE = 0, aF = 0;
            const float* hb = (mt ? Hs2 : Hs) + (jh << 12) + (lane << 1);
#pragma unroll
            for (int it = 0; it < 16; it++) {
                ull h0 = *(const ull*)(hb + (it * 4 + 0) * 64);
                ull h1 = *(const ull*)(hb + (it * 4 + 1) * 64);
                ull h2 = *(const ull*)(hb + (it * 4 + 2) * 64);
                ull h3 = *(const ull*)(hb + (it * 4 + 3) * 64);
                ulonglong2 xa, xb;
                xa = *(const ulonglong2*)(w0 + it * 8); xb = *(const ulonglong2*)(w0 + it * 8 + 4);
                f2(aA, h0, xa.x); f2(aA, h1, xa.y); f2(aA, h2, xb.x); f2(aA, h3, xb.y);
                xa = *(const ulonglong2*)(w1 + it * 8); xb = *(const ulonglong2*)(w1 + it * 8 + 4);
                f2(aB, h0, xa.x); f2(aB, h1, xa.y); f2(aB, h2, xb.x); f2(aB, h3, xb.y);
                xa = *(const ulonglong2*)(w2 + it * 8); xb = *(const ulonglong2*)(w2 + it * 8 + 4);
                f2(aC, h0, xa.x); f2(aC, h1, xa.y); f2(aC, h2, xb.x); f2(aC, h3, xb.y);
                xa = *(const ulonglong2*)(w3 + it * 8); xb = *(const ulonglong2*)(w3 + it * 8 + 4);
                f2(aD, h0, xa.x); f2(aD, h1, xa.y); f2(aD, h2, xb.x); f2(aD, h3, xb.y);
                xa = *(const ulonglong2*)(w4 + it * 8); xb = *(const ulonglong2*)(w4 + it * 8 + 4);
                f2(aE, h0, xa.x); f2(aE, h1, xa.y); f2(aE, h2, xb.x); f2(aE, h3, xb.y);
                xa = *(const ulonglong2*)(w5 + it * 8); xb = *(const ulonglong2*)(w5 + it * 8 + 4);
                f2(aF, h0, xa.x); f2(aF, h1, xa.y); f2(aF, h2, xb.x); f2(aF, h3, xb.y);
            }
            int ua = uh * 2, ub = uh * 2 + 1, col = mt * 2 + jh;
            parts[ua][0][col][lane] = fsum(aA);
            parts[ua][1][col][lane] = fsum(aB);
            parts[ua][2][col][lane] = fsum(aC);
            parts[ub][0][col][lane] = fsum(aD);
            parts[ub][1][col][lane] = fsum(aE);
            parts[ub][2][col][lane] = fsum(aF);
            __syncthreads();
            float hN = 0.f;
            if (w < 4) {
                float giR_ = parts[w][0][0][lane] + parts[w][0][1][lane] + biR;
                float giZ_ = parts[w][1][0][lane] + parts[w][1][1][lane] + biZ;
                float giN_ = parts[w][2][0][lane] + parts[w][2][1][lane] + biN;
                float ghR = parts[w][0][2][lane] + parts[w][0][3][lane] + bhR;
                float ghZ = parts[w][1][2][lane] + parts[w][1][3][lane] + bhZ;
                float ghN = parts[w][2][2][lane] + parts[w][2][3][lane] + bhN;
                float r = sigm(giR_ + ghR);
                float z = sigm(giZ_ + ghZ);
                float nn = tanhf(giN_ + r * ghN);
                hN = (1.f - z) * nn + z * Hs2[pidx];
                __stcg(&d_h2p[par ^ 1][pidx], hN);
            }
            __syncthreads();
            if (tid == 0) g_arrive(3);
            if (w < 4) d_h2all[t][ue * 32 + lane] = hN;
            if (tid == 0) g_waitge(3, 64u * (t + 1));
            __syncthreads();
        }
    }
}

// ---- output GEMM: M=4096(m=t*32+b) K=256 N=512, dup-B ----------------------
__global__ void __launch_bounds__(256) out_gemm(
    const float* __restrict__ outW, const float* __restrict__ outb,
    float* __restrict__ out) {
    __shared__ __align__(16) float As[8][128];
    __shared__ __align__(16) float Bs[8][256];
    int n0 = blockIdx.x << 7, m0 = blockIdx.y << 7;
    int tid = threadIdx.x, tx = tid & 31, ty = tid >> 5;
    int nl = tid & 127, kh = tid >> 7;
    const float* Wr = outW + (size_t)(n0 + nl) * 256;
    const float* h2f = (const float*)d_h2all;
    ull acc2[8][4];
#pragma unroll
    for (int i = 0; i < 8; i++)
#pragma unroll
        for (int j = 0; j < 4; j++) acc2[i][j] = 0ull;

    for (int k0 = 0; k0 < 256; k0 += 8) {
#pragma unroll
        for (int i = 0; i < 4; i++) {
            int e = tid + (i << 8);
            int ml = e & 127, kl = e >> 7;
            int m = m0 + ml;
            As[kl][ml] = h2f[(m >> 5) * 8192 + (k0 + kl) * 32 + (m & 31)];
        }
        float4 bv = __ldg((const float4*)(Wr + k0 + (kh << 2)));
        int kb = kh << 2, n2 = nl << 1;
        *(float2*)&Bs[kb + 0][n2] = make_float2(bv.x, bv.x);
        *(float2*)&Bs[kb + 1][n2] = make_float2(bv.y, bv.y);
        *(float2*)&Bs[kb + 2][n2] = make_float2(bv.z, bv.z);
        *(float2*)&Bs[kb + 3][n2] = make_float2(bv.w, bv.w);
        __syncthreads();
#pragma unroll
        for (int k = 0; k < 8; k++) {
            ulonglong2 qa0 = *(const ulonglong2*)&As[k][(ty << 4) + 0];
            ulonglong2 qa1 = *(const ulonglong2*)&As[k][(ty << 4) + 4];
            ulonglong2 qa2 = *(const ulonglong2*)&As[k][(ty << 4) + 8];
            ulonglong2 qa3 = *(const ulonglong2*)&As[k][(ty << 4) + 12];
            ulonglong2 qb0 = *(const ulonglong2*)&Bs[k][tx << 3];
            ulonglong2 qb1 = *(const ulonglong2*)&Bs[k][(tx << 3) + 4];
            ull bsp[4] = {qb0.x, qb0.y, qb1.x, qb1.y};
            ull am[8] = {qa0.x, qa0.y, qa1.x, qa1.y, qa2.x, qa2.y, qa3.x, qa3.y};
#pragma unroll
            for (int mp = 0; mp < 8; mp++) {
                f2(acc2[mp][0], am[mp], bsp[0]);
                f2(acc2[mp][1], am[mp], bsp[1]);
                f2(acc2[mp][2], am[mp], bsp[2]);
                f2(acc2[mp][3], am[mp], bsp[3]);
            }
        }
        __syncthreads();
    }
#pragma unroll
    for (int n = 0; n < 4; n++) {
        int v = n0 + (tx << 2) + n;
        float bias = __ldg(outb + v);
#pragma unroll
        for (int mp = 0; mp < 8; mp++) {
            float lo, hi;
            upk(acc2[mp][n], lo, hi);
            int m = m0 + (ty << 4) + (mp << 1);
            size_t b0 = (size_t)(m & 31) * 65536 + (m >> 5) * 512;
            size_t b1 = (size_t)((m + 1) & 31) * 65536 + ((m + 1) >> 5) * 512;
            out[b0 + v] = lo + bias;
            out[b1 + v] = hi + bias;
        }
    }
}

extern "C" void kernel_launch(void* const* d_in, const int* in_sizes, int n_in,
                              void* d_out, int out_size) {
    const float* src  = (const float*)d_in[0];
    const int*   tgt  = (const int*)d_in[1];
    const float* eWif = (const float*)d_in[2];
    const float* eWhf = (const float*)d_in[3];
    const float* ebif = (const float*)d_in[4];
    const float* ebhf = (const float*)d_in[5];
    const float* eWib = (const float*)d_in[6];
    const float* eWhb = (const float*)d_in[7];
    const float* ebib = (const float*)d_in[8];
    const float* ebhb = (const float*)d_in[9];
    const float* attW = (const float*)d_in[10];
    const float* emb  = (const float*)d_in[12];
    const float* W0i  = (const float*)d_in[13];
    const float* W0h  = (const float*)d_in[14];
    const float* b0i  = (const float*)d_in[15];
    const float* b0h  = (const float*)d_in[16];
    const float* W1i  = (const float*)d_in[17];
    const float* W1h  = (const float*)d_in[18];
    const float* b1i  = (const float*)d_in[19];
    const float* b1h  = (const float*)d_in[20];
    const float* outW = (const float*)d_in[21];
    const float* outb = (const float*)d_in[22];
    float* out = (float*)d_out;

    init_kernel<<<128, 256>>>();                       // 1
    vg_k<<<512, 256>>>(emb, W0i);                      // 2
    enc_gi_gemm<<<dim3(12, 128), 256>>>(src, eWif, eWib, ebif, ebib);  // 3
    enc_rnn<<<128, 256>>>(eWhf, ebhf, eWhb, ebhb);     // 4
    att_score<<<512, 256>>>(attW);                     // 5
    softmax_k<<<32, 256>>>();                          // 6
    ctx_k<<<512, 256>>>();                             // 7
    cg_k<<<768, 256>>>(W0i, b0i);                      // 8
    gi0_k<<<12288, 256>>>(tgt);                        // 9
    dec_rnn<<<128, 256>>>(W0h, b0h, W1i, b1i, W1h, b1h);  // 10
    out_gemm<<<dim3(4, 32), 256>>>(outW, outb, out);   // 11
}

// round 16
// speedup vs baseline: 1.0858x; 1.0858x over previous
#include <cuda_runtime.h>
#include <math.h>

typedef unsigned long long ull;

// B=32 C=512 S=512 T=128 V=512 E=128 EH=256 DH=256
// Attention softmax is invariant to the h2 term -> ctx constant over steps.
// Hidden states packed: element (j, lane) at (j>>1)*64 + lane*2 + (j&1) so a
// (h_j, h_{j+1}) pair for one lane is one 8-byte word -> feeds fma.rn.f32x2.

__device__ __align__(128) float d_giT[2][512][768 * 32];
__device__ __align__(128) float d_encT[512][512 * 32];
__device__ __align__(128) float d_hEnc[2][2][8192];
__device__ __align__(128) float d_score[512 * 32];
__device__ __align__(128) float d_w[512 * 32];
__device__ __align__(128) float d_ctx[512 * 32];
__device__ __align__(128) float d_vg[512 * 768];
__device__ __align__(128) float d_cg[768 * 32];
__device__ __align__(128) float d_gi0[128][768 * 32];
__device__ __align__(128) float d_h1all[128][8192];
__device__ __align__(128) float d_h1z[8192];
__device__ __align__(128) float d_h2p[2][8192];
__device__ __align__(128) float d_h2all[128][8192];
__device__ __align__(128) unsigned g_cnt[4 * 32];

__device__ __forceinline__ float sigm(float x) { return 1.f / (1.f + expf(-x)); }
__device__ __forceinline__ void f2(ull& d, ull a, ull b) {
    asm("fma.rn.f32x2 %0,%1,%2,%0;" : "+l"(d) : "l"(a), "l"(b));
}
__device__ __forceinline__ ull splat(float a) {
    ull s; asm("mov.b64 %0,{%1,%1};" : "=l"(s) : "f"(a)); return s;
}
__device__ __forceinline__ void upk(ull v, float& x, float& y) {
    asm("mov.b64 {%0,%1},%2;" : "=f"(x), "=f"(y) : "l"(v));
}
__device__ __forceinline__ float fsum(ull v) { float x, y; upk(v, x, y); return x + y; }

__device__ __forceinline__ void g_arrive(int id) {
    asm volatile("red.release.gpu.global.add.u32 [%0],%1;"
                 :: "l"(&g_cnt[id * 32]), "r"(1u) : "memory");
}
__device__ __forceinline__ void g_waitge(int id, unsigned target) {
    unsigned v;
    do {
        asm volatile("ld.acquire.gpu.global.u32 %0,[%1];"
                     : "=r"(v) : "l"(&g_cnt[id * 32]) : "memory");
    } while (v < target);
}

__device__ __forceinline__ void cp16(unsigned dst, const float* src) {
    asm volatile("cp.async.cg.shared.global [%0],[%1],16;"
                 :: "r"(dst), "l"(src) : "memory");
}

// 6-gate dot over one quarter (64 j) of a packed h vector.
__device__ __forceinline__ void gru_dots(const float* hb, const float* wg, ull* acc) {
#pragma unroll
    for (int it = 0; it < 8; it++) {
        ull h0 = *(const ull*)(hb + (it * 4 + 0) * 64);
        ull h1 = *(const ull*)(hb + (it * 4 + 1) * 64);
        ull h2 = *(const ull*)(hb + (it * 4 + 2) * 64);
        ull h3 = *(const ull*)(hb + (it * 4 + 3) * 64);
#pragma unroll
        for (int g = 0; g < 6; g++) {
            ulonglong2 xa = *(const ulonglong2*)(wg + g * 256 + it * 8);
            ulonglong2 xb = *(const ulonglong2*)(wg + g * 256 + it * 8 + 4);
            f2(acc[g], h0, xa.x); f2(acc[g], h1, xa.y);
            f2(acc[g], h2, xb.x); f2(acc[g], h3, xb.y);
        }
    }
}

__global__ void init_kernel() {
    int i = blockIdx.x * 256 + threadIdx.x;
    if (i < 32768) ((float*)d_hEnc)[i] = 0.f;
    if (i < 8192) d_h1z[i] = 0.f;
    if (i < 16384) ((float*)d_h2p)[i] = 0.f;
    if (i < 128) g_cnt[i] = 0u;
}

// ---- vocab part of dec0 input gates ----------------------------------------
__global__ void __launch_bounds__(256) vg_k(const float* __restrict__ emb,
                                            const float* __restrict__ W0i) {
    __shared__ float e[128];
    int v = blockIdx.x;
    if (threadIdx.x < 128) e[threadIdx.x] = __ldg(emb + v * 128 + threadIdx.x);
    __syncthreads();
    for (int g = threadIdx.x; g < 768; g += 256) {
        const float4* w = (const float4*)(W0i + (size_t)g * 640);
        float acc = 0.f;
#pragma unroll 8
        for (int k = 0; k < 32; k++) {
            float4 wv = __ldg(w + k);
            acc = fmaf(wv.x, e[4 * k], acc);
            acc = fmaf(wv.y, e[4 * k + 1], acc);
            acc = fmaf(wv.z, e[4 * k + 2], acc);
            acc = fmaf(wv.w, e[4 * k + 3], acc);
        }
        d_vg[v * 768 + g] = acc;
    }
}

// ---- encoder input GEMM: M=16384 K=512 N=1536, 3-stage pipeline ------------
__global__ void __launch_bounds__(256) enc_gi_gemm(
    const float* __restrict__ src, const float* __restrict__ Wf,
    const float* __restrict__ Wb, const float* __restrict__ bf,
    const float* __restrict__ bb) {
    __shared__ __align__(16) float As[3][16][128];
    __shared__ __align__(16) float Bs[3][16][128];
    int n0 = blockIdx.x << 7, m0 = blockIdx.y << 7;
    int bIdx = m0 >> 9, s0 = m0 & 511;
    int tid = threadIdx.x, tx = tid & 31, ty = tid >> 5;
    const float* aBase = src + (size_t)bIdx * 262144 + s0;
    int nl = tid & 127, kg = tid >> 7;
    int nld = n0 + nl;
    const float* Wr = (nld < 768) ? (Wf + (size_t)nld * 512)
                                  : (Wb + (size_t)(nld - 768) * 512);
    int kl0 = tid >> 5, mo0 = (tid & 31) << 2;
    int kl1 = (tid + 256) >> 5;

    ull acc2[8][4];
#pragma unroll
    for (int i = 0; i < 8; i++)
#pragma unroll
        for (int j = 0; j < 4; j++) acc2[i][j] = 0ull;

    // prologue: A tiles 0,1 in flight; B tile 0 staged
    cp16((unsigned)__cvta_generic_to_shared(&As[0][kl0][mo0]), aBase + kl0 * 512 + mo0);
    cp16((unsigned)__cvta_generic_to_shared(&As[0][kl1][mo0]), aBase + kl1 * 512 + mo0);
    asm volatile("cp.async.commit_group;" ::: "memory");
    cp16((unsigned)__cvta_generic_to_shared(&As[1][kl0][mo0]), aBase + (16 + kl0) * 512 + mo0);
    cp16((unsigned)__cvta_generic_to_shared(&As[1][kl1][mo0]), aBase + (16 + kl1) * 512 + mo0);
    asm volatile("cp.async.commit_group;" ::: "memory");
    {
        float4 bv0 = __ldg((const float4*)(Wr + (kg << 3)));
        float4 bv1 = __ldg((const float4*)(Wr + (kg << 3) + 4));
        int kb = kg << 3;
        Bs[0][kb + 0][nl] = bv0.x; Bs[0][kb + 1][nl] = bv0.y;
        Bs[0][kb + 2][nl] = bv0.z; Bs[0][kb + 3][nl] = bv0.w;
        Bs[0][kb + 4][nl] = bv1.x; Bs[0][kb + 5][nl] = bv1.y;
        Bs[0][kb + 6][nl] = bv1.z; Bs[0][kb + 7][nl] = bv1.w;
    }

    int cur = 0;
    for (int t = 0; t < 32; t++) {
        __syncthreads();   // old-buffer reads & prev B STS visible
        if (t < 30) {
            int nb = cur == 0 ? 2 : cur - 1;   // (t+2)%3
            int k0n = (t + 2) << 4;
            cp16((unsigned)__cvta_generic_to_shared(&As[nb][kl0][mo0]),
                 aBase + (k0n + kl0) * 512 + mo0);
            cp16((unsigned)__cvta_generic_to_shared(&As[nb][kl1][mo0]),
                 aBase + (k0n + kl1) * 512 + mo0);
            asm volatile("cp.async.commit_group;" ::: "memory");
        }
        float4 bv0, bv1;
        if (t < 31) {
            int k0n = (t + 1) << 4;
            bv0 = __ldg((const float4*)(Wr + k0n + (kg << 3)));
            bv1 = __ldg((const float4*)(Wr + k0n + (kg << 3) + 4));
        }
        if (t < 30)      asm volatile("cp.async.wait_group 2;" ::: "memory");
        else if (t < 31) asm volatile("cp.async.wait_group 1;" ::: "memory");
        else             asm volatile("cp.async.wait_group 0;" ::: "memory");
        __syncthreads();   // A(t) visible to all
#pragma unroll
        for (int k = 0; k < 16; k++) {
            ulonglong2 qa0 = *(const ulonglong2*)&As[cur][k][(ty << 4) + 0];
            ulonglong2 qa1 = *(const ulonglong2*)&As[cur][k][(ty << 4) + 4];
            ulonglong2 qa2 = *(const ulonglong2*)&As[cur][k][(ty << 4) + 8];
            ulonglong2 qa3 = *(const ulonglong2*)&As[cur][k][(ty << 4) + 12];
            float4 bv = *(const float4*)&Bs[cur][k][tx << 2];
            ull bsp[4] = {splat(bv.x), splat(bv.y), splat(bv.z), splat(bv.w)};
            ull am[8] = {qa0.x, qa0.y, qa1.x, qa1.y, qa2.x, qa2.y, qa3.x, qa3.y};
#pragma unroll
            for (int mp = 0; mp < 8; mp++) {
                f2(acc2[mp][0], am[mp], bsp[0]);
                f2(acc2[mp][1], am[mp], bsp[1]);
                f2(acc2[mp][2], am[mp], bsp[2]);
                f2(acc2[mp][3], am[mp], bsp[3]);
            }
        }
        if (t < 31) {
            int nbB = cur == 2 ? 0 : cur + 1;  // (t+1)%3
            int kb = kg << 3;
            Bs[nbB][kb + 0][nl] = bv0.x; Bs[nbB][kb + 1][nl] = bv0.y;
            Bs[nbB][kb + 2][nl] = bv0.z; Bs[nbB][kb + 3][nl] = bv0.w;
            Bs[nbB][kb + 4][nl] = bv1.x; Bs[nbB][kb + 5][nl] = bv1.y;
            Bs[nbB][kb + 6][nl] = bv1.z; Bs[nbB][kb + 7][nl] = bv1.w;
        }
        cur = cur == 2 ? 0 : cur + 1;
    }

#pragma unroll
    for (int n = 0; n < 4; n++) {
        int nn = n0 + (tx << 2) + n;
        int dA = nn >= 768;
        int row = nn - dA * 768;
        float bias = dA ? __ldg(bb + row) : __ldg(bf + row);
#pragma unroll
        for (int mp = 0; mp < 8; mp++) {
            float lo, hi;
            upk(acc2[mp][n], lo, hi);
            int s = s0 + (ty << 4) + (mp << 1);
            d_giT[dA][s][row * 32 + bIdx] = lo + bias;
            d_giT[dA][s + 1][row * 32 + bIdx] = hi + bias;
        }
    }
}

// ---- encoder recurrence: 128 blocks (64/dir) x 256 thr ---------------------
__global__ void __launch_bounds__(256) enc_rnn(
    const float* __restrict__ Whh_f, const float* __restrict__ bhh_f,
    const float* __restrict__ Whh_b, const float* __restrict__ bhh_b) {
    int dir = blockIdx.x >> 6, lb = blockIdx.x & 63;
    int u0 = lb * 4;
    const float* Whh = dir ? Whh_b : Whh_f;
    const float* bhh = dir ? bhh_b : bhh_f;
    __shared__ __align__(16) float Ws[12][256];
    __shared__ __align__(16) float Hs[8192];
    __shared__ float parts[4][3][4][32];
    int tid = threadIdx.x;
    for (int i = tid; i < 3072; i += 256) {
        int r = i >> 8, j = i & 255;
        Ws[r][j] = __ldg(Whh + (size_t)((r % 3) * 256 + u0 + r / 3) * 256 + j);
    }
    int w = tid >> 5, lane = tid & 31;
    int jq = w >> 1, uh = w & 1;
    int ue = u0 + (w & 3);
    float br = __ldg(bhh + ue), bz = __ldg(bhh + 256 + ue), bn = __ldg(bhh + 512 + ue);
    int pidx = (ue >> 1) * 64 + (lane << 1) + (ue & 1);
    const float* wg = Ws[uh * 6] + (jq << 6);
    int ua = uh * 2, ub = uh * 2 + 1;

    float giR = 0.f, giZ = 0.f, giN = 0.f;
    if (w < 4) {
        int sa0 = dir ? 511 : 0;
        giR = d_giT[dir][sa0][ue * 32 + lane];
        giZ = d_giT[dir][sa0][(256 + ue) * 32 + lane];
        giN = d_giT[dir][sa0][(512 + ue) * 32 + lane];
    }
    __syncthreads();

    for (int s = 0; s < 512; s++) {
        int par = s & 1;
        {
            const float4* srcp = (const float4*)d_hEnc[dir][par];
            float4* dst = (float4*)Hs;
            for (int i = tid; i < 2048; i += 256) dst[i] = __ldcg(srcp + i);
        }
        __syncthreads();
        ull acc[6] = {0, 0, 0, 0, 0, 0};
        gru_dots(Hs + (jq << 11) + (lane << 1), wg, acc);
#pragma unroll
        for (int g = 0; g < 3; g++) {
            parts[ua][g][jq][lane] = fsum(acc[g]);
            parts[ub][g][jq][lane] = fsum(acc[g + 3]);
        }
        __syncthreads();
        float hN = 0.f;
        int sa = dir ? (511 - s) : s;
        if (w < 4) {
            float gR = parts[w][0][0][lane] + parts[w][0][1][lane] +
                       parts[w][0][2][lane] + parts[w][0][3][lane];
            float gZ = parts[w][1][0][lane] + parts[w][1][1][lane] +
                       parts[w][1][2][lane] + parts[w][1][3][lane];
            float gN = parts[w][2][0][lane] + parts[w][2][1][lane] +
                       parts[w][2][2][lane] + parts[w][2][3][lane];
            float r = sigm(giR + gR + br);
            float z = sigm(giZ + gZ + bz);
            float nn = tanhf(giN + r * (gN + bn));
            hN = (1.f - z) * nn + z * Hs[pidx];
            __stcg(&d_hEnc[dir][par ^ 1][pidx], hN);
        }
        __syncthreads();
        if (tid == 0) g_arrive(dir);
        if (w < 4) {
            d_encT[sa][(dir * 256 + ue) * 32 + lane] = hN;
            if (s < 511) {
                int sn = dir ? (510 - s) : (s + 1);
                giR = d_giT[dir][sn][ue * 32 + lane];
                giZ = d_giT[dir][sn][(256 + ue) * 32 + lane];
                giN = d_giT[dir][sn][(512 + ue) * 32 + lane];
            }
        }
        if (tid == 0) g_waitge(dir, 64u * (s + 1));
        __syncthreads();
    }
}

// ---- attention (step-invariant) ----
__global__ void __launch_bounds__(256) att_score(const float* __restrict__ attW) {
    int s = blockIdx.x, q = threadIdx.x >> 5, b = threadIdx.x & 31;
    float p = 0.f;
    for (int d = q * 64; d < q * 64 + 64; d++)
        p = fmaf(d_encT[s][d * 32 + b], __ldg(attW + d), p);
    __shared__ float sm[8][32];
    sm[q][b] = p;
    __syncthreads();
    if (threadIdx.x < 32) {
        float v = 0.f;
#pragma unroll
        for (int i = 0; i < 8; i++) v += sm[i][threadIdx.x];
        d_score[s * 32 + threadIdx.x] = v;
    }
}

__global__ void __launch_bounds__(256) softmax_k() {
    int b = blockIdx.x, tid = threadIdx.x;
    float x1 = d_score[tid * 32 + b], x2 = d_score[(tid + 256) * 32 + b];
    __shared__ float sm[256];
    sm[tid] = fmaxf(x1, x2);
    __syncthreads();
    for (int o = 128; o > 0; o >>= 1) {
        if (tid < o) sm[tid] = fmaxf(sm[tid], sm[tid + o]);
        __syncthreads();
    }
    float M = sm[0];
    __syncthreads();
    float e1 = expf(x1 - M), e2 = expf(x2 - M);
    sm[tid] = e1 + e2;
    __syncthreads();
    for (int o = 128; o > 0; o >>= 1) {
        if (tid < o) sm[tid] += sm[tid + o];
        __syncthreads();
    }
    d_w[tid * 32 + b] = e1 / sm[0];
    d_w[(tid + 256) * 32 + b] = e2 / sm[0];
}

__global__ void __launch_bounds__(256) ctx_k() {
    int d = blockIdx.x, q = threadIdx.x >> 5, b = threadIdx.x & 31;
    float p = 0.f;
    for (int s = q * 64; s < q * 64 + 64; s++)
        p = fmaf(d_w[s * 32 + b], d_encT[s][d * 32 + b], p);
    __shared__ float sm[8][32];
    sm[q][b] = p;
    __syncthreads();
    if (threadIdx.x < 32) {
        float v = 0.f;
#pragma unroll
        for (int i = 0; i < 8; i++) v += sm[i][threadIdx.x];
        d_ctx[d * 32 + threadIdx.x] = v;
    }
}

__global__ void __launch_bounds__(256) cg_k(const float* __restrict__ W0i,
                                            const float* __restrict__ b0i) {
    int g = blockIdx.x, q = threadIdx.x >> 5, b = threadIdx.x & 31;
    const float* wrow = W0i + (size_t)g * 640 + 128;
    float p = 0.f;
    for (int d = q * 64; d < q * 64 + 64; d++)
        p = fmaf(d_ctx[d * 32 + b], __ldg(wrow + d), p);
    __shared__ float sm[8][32];
    sm[q][b] = p;
    __syncthreads();
    if (threadIdx.x < 32) {
        float v = __ldg(b0i + g);
#pragma unroll
        for (int i = 0; i < 8; i++) v += sm[i][threadIdx.x];
        d_cg[g * 32 + threadIdx.x] = v;
    }
}

__global__ void __launch_bounds__(256) gi0_k(const int* __restrict__ target) {
    int i = blockIdx.x * 256 + threadIdx.x;
    int t = i / 24576, rem = i - t * 24576;
    int g = rem >> 5, b = rem & 31;
    int tok = __ldg(target + b * 128 + t);
    d_gi0[t][g * 32 + b] = d_vg[tok * 768 + g] + d_cg[g * 32 + b];
}

// ---- decoder: blocks 0-63 = GRU0 chain, 64-127 = GRU1 chain ----------------
__global__ void __launch_bounds__(256) dec_rnn(
    const float* __restrict__ W0h, const float* __restrict__ b0h,
    const float* __restrict__ W1i, const float* __restrict__ b1i,
    const float* __restrict__ W1h, const float* __restrict__ b1h) {
    __shared__ __align__(16) float Wsm[24][256];
    __shared__ __align__(16) float Hs[8192];
    __shared__ __align__(16) float Hs2[8192];
    __shared__ float parts[4][3][4][32];
    int tid = threadIdx.x, w = tid >> 5, lane = tid & 31;

    if (blockIdx.x < 64) {   // ---------------- GRU0 chain -------------------
        int u0 = blockIdx.x * 4;
        for (int i = tid; i < 3072; i += 256) {
            int r = i >> 8, j = i & 255;
            Wsm[r][j] = __ldg(W0h + (size_t)((r % 3) * 256 + u0 + r / 3) * 256 + j);
        }
        int jq = w >> 1, uh = w & 1;
        int ue = u0 + (w & 3);
        float br = __ldg(b0h + ue), bz = __ldg(b0h + 256 + ue), bn = __ldg(b0h + 512 + ue);
        int pidx = (ue >> 1) * 64 + (lane << 1) + (ue & 1);
        const float* wg = Wsm[uh * 6] + (jq << 6);
        int ua = uh * 2, ub = uh * 2 + 1;
        float giR = 0.f, giZ = 0.f, giN = 0.f;
        if (w < 4) {
            giR = d_gi0[0][ue * 32 + lane];
            giZ = d_gi0[0][(256 + ue) * 32 + lane];
            giN = d_gi0[0][(512 + ue) * 32 + lane];
        }
        __syncthreads();
        for (int t = 0; t < 128; t++) {
            const float4* srcp = (const float4*)((t == 0) ? d_h1z : d_h1all[t - 1]);
            float4* dst = (float4*)Hs;
            for (int i = tid; i < 2048; i += 256) dst[i] = __ldcg(srcp + i);
            __syncthreads();
            ull acc[6] = {0, 0, 0, 0, 0, 0};
            gru_dots(Hs + (jq << 11) + (lane << 1), wg, acc);
#pragma unroll
            for (int g = 0; g < 3; g++) {
                parts[ua][g][jq][lane] = fsum(acc[g]);
                parts[ub][g][jq][lane] = fsum(acc[g + 3]);
            }
            __syncthreads();
            if (w < 4) {
                float gR = parts[w][0][0][lane] + parts[w][0][1][lane] +
                           parts[w][0][2][lane] + parts[w][0][3][lane] + br;
                float gZ = parts[w][1][0][lane] + parts[w][1][1][lane] +
                           parts[w][1][2][lane] + parts[w][1][3][lane] + bz;
                float gN = parts[w][2][0][lane] + parts[w][2][1][lane] +
                           parts[w][2][2][lane] + parts[w][2][3][lane] + bn;
                float r = sigm(giR + gR);
                float z = sigm(giZ + gZ);
                float nn = tanhf(giN + r * gN);
                float hN = (1.f - z) * nn + z * Hs[pidx];
                __stcg(&d_h1all[t][pidx], hN);
            }
            __syncthreads();
            if (tid == 0) g_arrive(2);
            if (w < 4 && t < 127) {
                giR = d_gi0[t + 1][ue * 32 + lane];
                giZ = d_gi0[t + 1][(256 + ue) * 32 + lane];
                giN = d_gi0[t + 1][(512 + ue) * 32 + lane];
            }
            if (tid == 0) g_waitge(2, 64u * (t + 1));
            __syncthreads();
        }
    } else {                 // ---------------- GRU1 chain -------------------
        int u0 = (blockIdx.x - 64) * 4;
        for (int i = tid; i < 3072; i += 256) {
            int r = i >> 8, j = i & 255;
            Wsm[r][j] = __ldg(W1i + (size_t)((r % 3) * 256 + u0 + r / 3) * 256 + j);
            Wsm[12 + r][j] = __ldg(W1h + (size_t)((r % 3) * 256 + u0 + r / 3) * 256 + j);
        }
        int mt = w >> 2, jh = (w >> 1) & 1, uh = w & 1;
        int ue = u0 + (w & 3);
        float biR = __ldg(b1i + ue), biZ = __ldg(b1i + 256 + ue), biN = __ldg(b1i + 512 + ue);
        float bhR = __ldg(b1h + ue), bhZ = __ldg(b1h + 256 + ue), bhN = __ldg(b1h + 512 + ue);
        int pidx = (ue >> 1) * 64 + (lane << 1) + (ue & 1);
        int rb = mt * 12 + uh * 6;
        const float* w0 = Wsm[rb + 0] + (jh << 7);
        const float* w1 = Wsm[rb + 1] + (jh << 7);
        const float* w2 = Wsm[rb + 2] + (jh << 7);
        const float* w3 = Wsm[rb + 3] + (jh << 7);
        const float* w4 = Wsm[rb + 4] + (jh << 7);
        const float* w5 = Wsm[rb + 5] + (jh << 7);
        __syncthreads();
        for (int t = 0; t < 128; t++) {
            int par = t & 1;
            {
                const float4* srcp = (const float4*)d_h2p[par];
                float4* dst = (float4*)Hs2;
                for (int i = tid; i < 2048; i += 256) dst[i] = __ldcg(srcp + i);
            }
            __syncthreads();
            if (mt == 0) {
                if (tid == 0) g_waitge(2, 64u * (t + 1));
                asm volatile("bar.sync 1,128;" ::: "memory");
                const float4* srcp = (const float4*)d_h1all[t];
                float4* dst = (float4*)Hs;
                for (int i = tid; i < 2048; i += 128) dst[i] = __ldcg(srcp + i);
                asm volatile("bar.sync 1,128;" ::: "memory");
            }
            ull aA = 0, aB = 0, aC = 0, aD = 0, aE = 0, aF = 0;
            const float* hb = (mt ? Hs2 : Hs) + (jh << 12) + (lane << 1);
#pragma unroll
            for (int it = 0; it < 16; it++) {
                ull h0 = *(const ull*)(hb + (it * 4 + 0) * 64);
                ull h1 = *(const ull*)(hb + (it * 4 + 1) * 64);
                ull h2 = *(const ull*)(hb + (it * 4 + 2) * 64);
                ull h3 = *(const ull*)(hb + (it * 4 + 3) * 64);
                ulonglong2 xa, xb;
                xa = *(const ulonglong2*)(w0 + it * 8); xb = *(const ulonglong2*)(w0 + it * 8 + 4);
                f2(aA, h0, xa.x); f2(aA, h1, xa.y); f2(aA, h2, xb.x); f2(aA, h3, xb.y);
                xa = *(const ulonglong2*)(w1 + it * 8); xb = *(const ulonglong2*)(w1 + it * 8 + 4);
                f2(aB, h0, xa.x); f2(aB, h1, xa.y); f2(aB, h2, xb.x); f2(aB, h3, xb.y);
                xa = *(const ulonglong2*)(w2 + it * 8); xb = *(const ulonglong2*)(w2 + it * 8 + 4);
                f2(aC, h0, xa.x); f2(aC, h1, xa.y); f2(aC, h2, xb.x); f2(aC, h3, xb.y);
                xa = *(const ulonglong2*)(w3 + it * 8); xb = *(const ulonglong2*)(w3 + it * 8 + 4);
                f2(aD, h0, xa.x); f2(aD, h1, xa.y); f2(aD, h2, xb.x); f2(aD, h3, xb.y);
                xa = *(const ulonglong2*)(w4 + it * 8); xb = *(const ulonglong2*)(w4 + it * 8 + 4);
                f2(aE, h0, xa.x); f2(aE, h1, xa.y); f2(aE, h2, xb.x); f2(aE, h3, xb.y);
                xa = *(const ulonglong2*)(w5 + it * 8); xb = *(const ulonglong2*)(w5 + it * 8 + 4);
                f2(aF, h0, xa.x); f2(aF, h1, xa.y); f2(aF, h2, xb.x); f2(aF, h3, xb.y);
            }
            int ua = uh * 2, ub = uh * 2 + 1, col = mt * 2 + jh;
            parts[ua][0][col][lane] = fsum(aA);
            parts[ua][1][col][lane] = fsum(aB);
            parts[ua][2][col][lane] = fsum(aC);
            parts[ub][0][col][lane] = fsum(aD);
            parts[ub][1][col][lane] = fsum(aE);
            parts[ub][2][col][lane] = fsum(aF);
            __syncthreads();
            float hN = 0.f;
            if (w < 4) {
                float giR_ = parts[w][0][0][lane] + parts[w][0][1][lane] + biR;
                float giZ_ = parts[w][1][0][lane] + parts[w][1][1][lane] + biZ;
                float giN_ = parts[w][2][0][lane] + parts[w][2][1][lane] + biN;
                float ghR = parts[w][0][2][lane] + parts[w][0][3][lane] + bhR;
                float ghZ = parts[w][1][2][lane] + parts[w][1][3][lane] + bhZ;
                float ghN = parts[w][2][2][lane] + parts[w][2][3][lane] + bhN;
                float r = sigm(giR_ + ghR);
                float z = sigm(giZ_ + ghZ);
                float nn = tanhf(giN_ + r * ghN);
                hN = (1.f - z) * nn + z * Hs2[pidx];
                __stcg(&d_h2p[par ^ 1][pidx], hN);
            }
            __syncthreads();
            if (tid == 0) g_arrive(3);
            if (w < 4) d_h2all[t][ue * 32 + lane] = hN;
            if (tid == 0) g_waitge(3, 64u * (t + 1));
            __syncthreads();
        }
    }
}

// ---- output GEMM: M=4096(m=t*32+b) K=256 N=512 ----
__global__ void __launch_bounds__(256) out_gemm(
    const float* __restrict__ outW, const float* __restrict__ outb,
    float* __restrict__ out) {
    __shared__ __align__(16) float As[8][128];
    __shared__ __align__(16) float Bs[8][128];
    int n0 = blockIdx.x << 7, m0 = blockIdx.y << 7;
    int tid = threadIdx.x, tx = tid & 31, ty = tid >> 5;
    int nl = tid & 127, kh = tid >> 7;
    const float* Wr = outW + (size_t)(n0 + nl) * 256;
    const float* h2f = (const float*)d_h2all;
    ull acc2[8][4];
#pragma unroll
    for (int i = 0; i < 8; i++)
#pragma unroll
        for (int j = 0; j < 4; j++) acc2[i][j] = 0ull;

    for (int k0 = 0; k0 < 256; k0 += 8) {
#pragma unroll
        for (int i = 0; i < 4; i++) {
            int e = tid + (i << 8);
            int ml = e & 127, kl = e >> 7;
            int m = m0 + ml;
            As[kl][ml] = h2f[(m >> 5) * 8192 + (k0 + kl) * 32 + (m & 31)];
        }
        float4 bv = __ldg((const float4*)(Wr + k0 + (kh << 2)));
        Bs[(kh << 2) + 0][nl] = bv.x;
        Bs[(kh << 2) + 1][nl] = bv.y;
        Bs[(kh << 2) + 2][nl] = bv.z;
        Bs[(kh << 2) + 3][nl] = bv.w;
        __syncthreads();
#pragma unroll
        for (int k = 0; k < 8; k++) {
            ulonglong2 qa0 = *(const ulonglong2*)&As[k][(ty << 4) + 0];
            ulonglong2 qa1 = *(const ulonglong2*)&As[k][(ty << 4) + 4];
            ulonglong2 qa2 = *(const ulonglong2*)&As[k][(ty << 4) + 8];
            ulonglong2 qa3 = *(const ulonglong2*)&As[k][(ty << 4) + 12];
            float4 bv2 = *(const float4*)&Bs[k][tx << 2];
            ull bsp[4] = {splat(bv2.x), splat(bv2.y), splat(bv2.z), splat(bv2.w)};
            ull am[8] = {qa0.x, qa0.y, qa1.x, qa1.y, qa2.x, qa2.y, qa3.x, qa3.y};
#pragma unroll
            for (int mp = 0; mp < 8; mp++) {
                f2(acc2[mp][0], am[mp], bsp[0]);
                f2(acc2[mp][1], am[mp], bsp[1]);
                f2(acc2[mp][2], am[mp], bsp[2]);
                f2(acc2[mp][3], am[mp], bsp[3]);
            }
        }
        __syncthreads();
    }
#pragma unroll
    for (int n = 0; n < 4; n++) {
        int v = n0 + (tx << 2) + n;
        float bias = __ldg(outb + v);
#pragma unroll
        for (int mp = 0; mp < 8; mp++) {
            float lo, hi;
            upk(acc2[mp][n], lo, hi);
            int m = m0 + (ty << 4) + (mp << 1);
            size_t b0 = (size_t)(m & 31) * 65536 + (m >> 5) * 512;
            size_t b1 = (size_t)((m + 1) & 31) * 65536 + ((m + 1) >> 5) * 512;
            out[b0 + v] = lo + bias;
            out[b1 + v] = hi + bias;
        }
    }
}

extern "C" void kernel_launch(void* const* d_in, const int* in_sizes, int n_in,
                              void* d_out, int out_size) {
    const float* src  = (const float*)d_in[0];
    const int*   tgt  = (const int*)d_in[1];
    const float* eWif = (const float*)d_in[2];
    const float* eWhf = (const float*)d_in[3];
    const float* ebif = (const float*)d_in[4];
    const float* ebhf = (const float*)d_in[5];
    const float* eWib = (const float*)d_in[6];
    const float* eWhb = (const float*)d_in[7];
    const float* ebib = (const float*)d_in[8];
    const float* ebhb = (const float*)d_in[9];
    const float* attW = (const float*)d_in[10];
    const float* emb  = (const float*)d_in[12];
    const float* W0i  = (const float*)d_in[13];
    const float* W0h  = (const float*)d_in[14];
    const float* b0i  = (const float*)d_in[15];
    const float* b0h  = (const float*)d_in[16];
    const float* W1i  = (const float*)d_in[17];
    const float* W1h  = (const float*)d_in[18];
    const float* b1i  = (const float*)d_in[19];
    const float* b1h  = (const float*)d_in[20];
    const float* outW = (const float*)d_in[21];
    const float* outb = (const float*)d_in[22];
    float* out = (float*)d_out;

    init_kernel<<<128, 256>>>();                       // 1
    vg_k<<<512, 256>>>(emb, W0i);                      // 2
    enc_gi_gemm<<<dim3(12, 128), 256>>>(src, eWif, eWib, ebif, ebib);  // 3
    enc_rnn<<<128, 256>>>(eWhf, ebhf, eWhb, ebhb);     // 4
    att_score<<<512, 256>>>(attW);                     // 5
    softmax_k<<<32, 256>>>();                          // 6
    ctx_k<<<512, 256>>>();                             // 7
    cg_k<<<768, 256>>>(W0i, b0i);                      // 8
    gi0_k<<<12288, 256>>>(tgt);                        // 9
    dec_rnn<<<128, 256>>>(W0h, b0h, W1i, b1i, W1h, b1h);  // 10
    out_gemm<<<dim3(4, 32), 256>>>(outW, outb, out);   // 11
}

// round 17
// speedup vs baseline: 1.0927x; 1.0064x over previous
#include <cuda_runtime.h>
#include <math.h>

typedef unsigned long long ull;

// B=32 C=512 S=512 T=128 V=512 E=128 EH=256 DH=256
// Attention softmax is invariant to the h2 term -> ctx constant over steps.
// Hidden states packed: element (j, lane) at (j>>1)*64 + lane*2 + (j&1) so a
// (h_j, h_{j+1}) pair for one lane is one 8-byte word -> feeds fma.rn.f32x2.

__device__ __align__(128) float d_giT[2][512][768 * 32];
__device__ __align__(128) float d_encT[512][512 * 32];
__device__ __align__(128) float d_hEnc[2][2][8192];
__device__ __align__(128) float d_score[512 * 32];
__device__ __align__(128) float d_w[512 * 32];
__device__ __align__(128) float d_ctx[512 * 32];
__device__ __align__(128) float d_vg[512 * 768];
__device__ __align__(128) float d_cg[768 * 32];
__device__ __align__(128) float d_gi0[128][768 * 32];
__device__ __align__(128) float d_h1all[128][8192];
__device__ __align__(128) float d_h1z[8192];
__device__ __align__(128) float d_h2p[2][8192];
__device__ __align__(128) float d_h2all[128][8192];
__device__ __align__(128) unsigned g_cnt[4 * 32];

__device__ __forceinline__ float sigm(float x) { return 1.f / (1.f + expf(-x)); }
__device__ __forceinline__ void f2(ull& d, ull a, ull b) {
    asm("fma.rn.f32x2 %0,%1,%2,%0;" : "+l"(d) : "l"(a), "l"(b));
}
__device__ __forceinline__ ull splat(float a) {
    ull s; asm("mov.b64 %0,{%1,%1};" : "=l"(s) : "f"(a)); return s;
}
__device__ __forceinline__ void upk(ull v, float& x, float& y) {
    asm("mov.b64 {%0,%1},%2;" : "=f"(x), "=f"(y) : "l"(v));
}
__device__ __forceinline__ float fsum(ull v) { float x, y; upk(v, x, y); return x + y; }

__device__ __forceinline__ void g_arrive(int id) {
    asm volatile("red.release.gpu.global.add.u32 [%0],%1;"
                 :: "l"(&g_cnt[id * 32]), "r"(1u) : "memory");
}
__device__ __forceinline__ void g_waitge(int id, unsigned target) {
    unsigned v;
    do {
        asm volatile("ld.acquire.gpu.global.u32 %0,[%1];"
                     : "=r"(v) : "l"(&g_cnt[id * 32]) : "memory");
    } while (v < target);
}

__device__ __forceinline__ void cp16(unsigned dst, const float* src) {
    asm volatile("cp.async.cg.shared.global [%0],[%1],16;"
                 :: "r"(dst), "l"(src) : "memory");
}

// 6-gate dot over one quarter (64 j) of a packed h vector.
__device__ __forceinline__ void gru_dots(const float* hb, const float* wg, ull* acc) {
#pragma unroll
    for (int it = 0; it < 8; it++) {
        ull h0 = *(const ull*)(hb + (it * 4 + 0) * 64);
        ull h1 = *(const ull*)(hb + (it * 4 + 1) * 64);
        ull h2 = *(const ull*)(hb + (it * 4 + 2) * 64);
        ull h3 = *(const ull*)(hb + (it * 4 + 3) * 64);
#pragma unroll
        for (int g = 0; g < 6; g++) {
            ulonglong2 xa = *(const ulonglong2*)(wg + g * 256 + it * 8);
            ulonglong2 xb = *(const ulonglong2*)(wg + g * 256 + it * 8 + 4);
            f2(acc[g], h0, xa.x); f2(acc[g], h1, xa.y);
            f2(acc[g], h2, xb.x); f2(acc[g], h3, xb.y);
        }
    }
}

__global__ void init_kernel() {
    int i = blockIdx.x * 256 + threadIdx.x;
    if (i < 32768) ((float*)d_hEnc)[i] = 0.f;
    if (i < 8192) d_h1z[i] = 0.f;
    if (i < 16384) ((float*)d_h2p)[i] = 0.f;
    if (i < 128) g_cnt[i] = 0u;
}

// ---- vocab part of dec0 input gates ----------------------------------------
__global__ void __launch_bounds__(256) vg_k(const float* __restrict__ emb,
                                            const float* __restrict__ W0i) {
    __shared__ float e[128];
    int v = blockIdx.x;
    if (threadIdx.x < 128) e[threadIdx.x] = __ldg(emb + v * 128 + threadIdx.x);
    __syncthreads();
    for (int g = threadIdx.x; g < 768; g += 256) {
        const float4* w = (const float4*)(W0i + (size_t)g * 640);
        float acc = 0.f;
#pragma unroll 8
        for (int k = 0; k < 32; k++) {
            float4 wv = __ldg(w + k);
            acc = fmaf(wv.x, e[4 * k], acc);
            acc = fmaf(wv.y, e[4 * k + 1], acc);
            acc = fmaf(wv.z, e[4 * k + 2], acc);
            acc = fmaf(wv.w, e[4 * k + 3], acc);
        }
        d_vg[v * 768 + g] = acc;
    }
}

// ---- encoder input GEMM: M=16384 K=512 N=1536 -------------------------------
// 3-stage cp.async pipeline, ONE __syncthreads per 16-k tile.
__global__ void __launch_bounds__(256) enc_gi_gemm(
    const float* __restrict__ src, const float* __restrict__ Wf,
    const float* __restrict__ Wb, const float* __restrict__ bf,
    const float* __restrict__ bb) {
    __shared__ __align__(16) float As[3][16][128];
    __shared__ __align__(16) float Bs[3][16][128];
    int n0 = blockIdx.x << 7, m0 = blockIdx.y << 7;
    int bIdx = m0 >> 9, s0 = m0 & 511;
    int tid = threadIdx.x, tx = tid & 31, ty = tid >> 5;
    const float* aBase = src + (size_t)bIdx * 262144 + s0;
    int nl = tid & 127, kg = tid >> 7;
    int nld = n0 + nl;
    const float* Wr = (nld < 768) ? (Wf + (size_t)nld * 512)
                                  : (Wb + (size_t)(nld - 768) * 512);
    int kl0 = tid >> 5, mo0 = (tid & 31) << 2;
    int kl1 = (tid + 256) >> 5;

    ull acc2[8][4];
#pragma unroll
    for (int i = 0; i < 8; i++)
#pragma unroll
        for (int j = 0; j < 4; j++) acc2[i][j] = 0ull;

    // prologue: A tiles 0,1 in flight (groups 0,1); B tile 0 staged
    cp16((unsigned)__cvta_generic_to_shared(&As[0][kl0][mo0]), aBase + kl0 * 512 + mo0);
    cp16((unsigned)__cvta_generic_to_shared(&As[0][kl1][mo0]), aBase + kl1 * 512 + mo0);
    asm volatile("cp.async.commit_group;" ::: "memory");
    cp16((unsigned)__cvta_generic_to_shared(&As[1][kl0][mo0]), aBase + (16 + kl0) * 512 + mo0);
    cp16((unsigned)__cvta_generic_to_shared(&As[1][kl1][mo0]), aBase + (16 + kl1) * 512 + mo0);
    asm volatile("cp.async.commit_group;" ::: "memory");
    {
        float4 bv0 = __ldg((const float4*)(Wr + (kg << 3)));
        float4 bv1 = __ldg((const float4*)(Wr + (kg << 3) + 4));
        int kb = kg << 3;
        Bs[0][kb + 0][nl] = bv0.x; Bs[0][kb + 1][nl] = bv0.y;
        Bs[0][kb + 2][nl] = bv0.z; Bs[0][kb + 3][nl] = bv0.w;
        Bs[0][kb + 4][nl] = bv1.x; Bs[0][kb + 5][nl] = bv1.y;
        Bs[0][kb + 6][nl] = bv1.z; Bs[0][kb + 7][nl] = bv1.w;
    }

    int cur = 0;
    for (int t = 0; t < 32; t++) {
        // drain group t (2 groups in flight except at the tail)
        if (t < 31) asm volatile("cp.async.wait_group 1;" ::: "memory");
        else        asm volatile("cp.async.wait_group 0;" ::: "memory");
        __syncthreads();   // A(t) + B-STS(t) visible; prior-stage reads done
        // B for tile t+1 (registers; STS after compute)
        float4 bv0, bv1;
        if (t < 31) {
            int k0n = (t + 1) << 4;
            bv0 = __ldg((const float4*)(Wr + k0n + (kg << 3)));
            bv1 = __ldg((const float4*)(Wr + k0n + (kg << 3) + 4));
        }
#pragma unroll
        for (int k = 0; k < 16; k++) {
            ulonglong2 qa0 = *(const ulonglong2*)&As[cur][k][(ty << 4) + 0];
            ulonglong2 qa1 = *(const ulonglong2*)&As[cur][k][(ty << 4) + 4];
            ulonglong2 qa2 = *(const ulonglong2*)&As[cur][k][(ty << 4) + 8];
            ulonglong2 qa3 = *(const ulonglong2*)&As[cur][k][(ty << 4) + 12];
            float4 bv = *(const float4*)&Bs[cur][k][tx << 2];
            ull bsp[4] = {splat(bv.x), splat(bv.y), splat(bv.z), splat(bv.w)};
            ull am[8] = {qa0.x, qa0.y, qa1.x, qa1.y, qa2.x, qa2.y, qa3.x, qa3.y};
#pragma unroll
            for (int mp = 0; mp < 8; mp++) {
                f2(acc2[mp][0], am[mp], bsp[0]);
                f2(acc2[mp][1], am[mp], bsp[1]);
                f2(acc2[mp][2], am[mp], bsp[2]);
                f2(acc2[mp][3], am[mp], bsp[3]);
            }
        }
        if (t < 30) {   // A tile t+2 -> stage (t+2)%3 (last read ended iter t-1)
            int nb = cur == 0 ? 2 : cur - 1;
            int k0n = (t + 2) << 4;
            cp16((unsigned)__cvta_generic_to_shared(&As[nb][kl0][mo0]),
                 aBase + (k0n + kl0) * 512 + mo0);
            cp16((unsigned)__cvta_generic_to_shared(&As[nb][kl1][mo0]),
                 aBase + (k0n + kl1) * 512 + mo0);
            asm volatile("cp.async.commit_group;" ::: "memory");
        }
        if (t < 31) {   // B STS tile t+1 -> stage (t+1)%3 (last read iter t-2)
            int nbB = cur == 2 ? 0 : cur + 1;
            int kb = kg << 3;
            Bs[nbB][kb + 0][nl] = bv0.x; Bs[nbB][kb + 1][nl] = bv0.y;
            Bs[nbB][kb + 2][nl] = bv0.z; Bs[nbB][kb + 3][nl] = bv0.w;
            Bs[nbB][kb + 4][nl] = bv1.x; Bs[nbB][kb + 5][nl] = bv1.y;
            Bs[nbB][kb + 6][nl] = bv1.z; Bs[nbB][kb + 7][nl] = bv1.w;
        }
        cur = cur == 2 ? 0 : cur + 1;
    }

#pragma unroll
    for (int n = 0; n < 4; n++) {
        int nn = n0 + (tx << 2) + n;
        int dA = nn >= 768;
        int row = nn - dA * 768;
        float bias = dA ? __ldg(bb + row) : __ldg(bf + row);
#pragma unroll
        for (int mp = 0; mp < 8; mp++) {
            float lo, hi;
            upk(acc2[mp][n], lo, hi);
            int s = s0 + (ty << 4) + (mp << 1);
            d_giT[dA][s][row * 32 + bIdx] = lo + bias;
            d_giT[dA][s + 1][row * 32 + bIdx] = hi + bias;
        }
    }
}

// ---- encoder recurrence: 128 blocks (64/dir) x 256 thr ---------------------
__global__ void __launch_bounds__(256) enc_rnn(
    const float* __restrict__ Whh_f, const float* __restrict__ bhh_f,
    const float* __restrict__ Whh_b, const float* __restrict__ bhh_b) {
    int dir = blockIdx.x >> 6, lb = blockIdx.x & 63;
    int u0 = lb * 4;
    const float* Whh = dir ? Whh_b : Whh_f;
    const float* bhh = dir ? bhh_b : bhh_f;
    __shared__ __align__(16) float Ws[12][256];
    __shared__ __align__(16) float Hs[8192];
    __shared__ float parts[4][3][4][32];
    int tid = threadIdx.x;
    for (int i = tid; i < 3072; i += 256) {
        int r = i >> 8, j = i & 255;
        Ws[r][j] = __ldg(Whh + (size_t)((r % 3) * 256 + u0 + r / 3) * 256 + j);
    }
    int w = tid >> 5, lane = tid & 31;
    int jq = w >> 1, uh = w & 1;
    int ue = u0 + (w & 3);
    float br = __ldg(bhh + ue), bz = __ldg(bhh + 256 + ue), bn = __ldg(bhh + 512 + ue);
    int pidx = (ue >> 1) * 64 + (lane << 1) + (ue & 1);
    const float* wg = Ws[uh * 6] + (jq << 6);
    int ua = uh * 2, ub = uh * 2 + 1;

    float giR = 0.f, giZ = 0.f, giN = 0.f;
    if (w < 4) {
        int sa0 = dir ? 511 : 0;
        giR = d_giT[dir][sa0][ue * 32 + lane];
        giZ = d_giT[dir][sa0][(256 + ue) * 32 + lane];
        giN = d_giT[dir][sa0][(512 + ue) * 32 + lane];
    }
    __syncthreads();

    for (int s = 0; s < 512; s++) {
        int par = s & 1;
        {
            const float4* srcp = (const float4*)d_hEnc[dir][par];
            float4* dst = (float4*)Hs;
            for (int i = tid; i < 2048; i += 256) dst[i] = __ldcg(srcp + i);
        }
        __syncthreads();
        ull acc[6] = {0, 0, 0, 0, 0, 0};
        gru_dots(Hs + (jq << 11) + (lane << 1), wg, acc);
#pragma unroll
        for (int g = 0; g < 3; g++) {
            parts[ua][g][jq][lane] = fsum(acc[g]);
            parts[ub][g][jq][lane] = fsum(acc[g + 3]);
        }
        __syncthreads();
        float hN = 0.f;
        int sa = dir ? (511 - s) : s;
        if (w < 4) {
            float gR = parts[w][0][0][lane] + parts[w][0][1][lane] +
                       parts[w][0][2][lane] + parts[w][0][3][lane];
            float gZ = parts[w][1][0][lane] + parts[w][1][1][lane] +
                       parts[w][1][2][lane] + parts[w][1][3][lane];
            float gN = parts[w][2][0][lane] + parts[w][2][1][lane] +
                       parts[w][2][2][lane] + parts[w][2][3][lane];
            float r = sigm(giR + gR + br);
            float z = sigm(giZ + gZ + bz);
            float nn = tanhf(giN + r * (gN + bn));
            hN = (1.f - z) * nn + z * Hs[pidx];
            __stcg(&d_hEnc[dir][par ^ 1][pidx], hN);
        }
        __syncthreads();
        if (tid == 0) g_arrive(dir);
        if (w < 4) {
            d_encT[sa][(dir * 256 + ue) * 32 + lane] = hN;
            if (s < 511) {
                int sn = dir ? (510 - s) : (s + 1);
                giR = d_giT[dir][sn][ue * 32 + lane];
                giZ = d_giT[dir][sn][(256 + ue) * 32 + lane];
                giN = d_giT[dir][sn][(512 + ue) * 32 + lane];
            }
        }
        if (tid == 0) g_waitge(dir, 64u * (s + 1));
        __syncthreads();
    }
}

// ---- attention (step-invariant) ----
__global__ void __launch_bounds__(256) att_score(const float* __restrict__ attW) {
    int s = blockIdx.x, q = threadIdx.x >> 5, b = threadIdx.x & 31;
    float p = 0.f;
    for (int d = q * 64; d < q * 64 + 64; d++)
        p = fmaf(d_encT[s][d * 32 + b], __ldg(attW + d), p);
    __shared__ float sm[8][32];
    sm[q][b] = p;
    __syncthreads();
    if (threadIdx.x < 32) {
        float v = 0.f;
#pragma unroll
        for (int i = 0; i < 8; i++) v += sm[i][threadIdx.x];
        d_score[s * 32 + threadIdx.x] = v;
    }
}

__global__ void __launch_bounds__(256) softmax_k() {
    int b = blockIdx.x, tid = threadIdx.x;
    float x1 = d_score[tid * 32 + b], x2 = d_score[(tid + 256) * 32 + b];
    __shared__ float sm[256];
    sm[tid] = fmaxf(x1, x2);
    __syncthreads();
    for (int o = 128; o > 0; o >>= 1) {
        if (tid < o) sm[tid] = fmaxf(sm[tid], sm[tid + o]);
        __syncthreads();
    }
    float M = sm[0];
    __syncthreads();
    float e1 = expf(x1 - M), e2 = expf(x2 - M);
    sm[tid] = e1 + e2;
    __syncthreads();
    for (int o = 128; o > 0; o >>= 1) {
        if (tid < o) sm[tid] += sm[tid + o];
        __syncthreads();
    }
    d_w[tid * 32 + b] = e1 / sm[0];
    d_w[(tid + 256) * 32 + b] = e2 / sm[0];
}

__global__ void __launch_bounds__(256) ctx_k() {
    int d = blockIdx.x, q = threadIdx.x >> 5, b = threadIdx.x & 31;
    float p = 0.f;
    for (int s = q * 64; s < q * 64 + 64; s++)
        p = fmaf(d_w[s * 32 + b], d_encT[s][d * 32 + b], p);
    __shared__ float sm[8][32];
    sm[q][b] = p;
    __syncthreads();
    if (threadIdx.x < 32) {
        float v = 0.f;
#pragma unroll
        for (int i = 0; i < 8; i++) v += sm[i][threadIdx.x];
        d_ctx[d * 32 + threadIdx.x] = v;
    }
}

__global__ void __launch_bounds__(256) cg_k(const float* __restrict__ W0i,
                                            const float* __restrict__ b0i) {
    int g = blockIdx.x, q = threadIdx.x >> 5, b = threadIdx.x & 31;
    const float* wrow = W0i + (size_t)g * 640 + 128;
    float p = 0.f;
    for (int d = q * 64; d < q * 64 + 64; d++)
        p = fmaf(d_ctx[d * 32 + b], __ldg(wrow + d), p);
    __shared__ float sm[8][32];
    sm[q][b] = p;
    __syncthreads();
    if (threadIdx.x < 32) {
        float v = __ldg(b0i + g);
#pragma unroll
        for (int i = 0; i < 8; i++) v += sm[i][threadIdx.x];
        d_cg[g * 32 + threadIdx.x] = v;
    }
}

__global__ void __launch_bounds__(256) gi0_k(const int* __restrict__ target) {
    int i = blockIdx.x * 256 + threadIdx.x;
    int t = i / 24576, rem = i - t * 24576;
    int g = rem >> 5, b = rem & 31;
    int tok = __ldg(target + b * 128 + t);
    d_gi0[t][g * 32 + b] = d_vg[tok * 768 + g] + d_cg[g * 32 + b];
}

// ---- decoder: blocks 0-63 = GRU0 chain, 64-127 = GRU1 chain ----------------
__global__ void __launch_bounds__(256) dec_rnn(
    const float* __restrict__ W0h, const float* __restrict__ b0h,
    const float* __restrict__ W1i, const float* __restrict__ b1i,
    const float* __restrict__ W1h, const float* __restrict__ b1h) {
    __shared__ __align__(16) float Wsm[24][256];
    __shared__ __align__(16) float Hs[8192];
    __shared__ __align__(16) float Hs2[8192];
    __shared__ float parts[4][3][4][32];
    int tid = threadIdx.x, w = tid >> 5, lane = tid & 31;

    if (blockIdx.x < 64) {   // ---------------- GRU0 chain -------------------
        int u0 = blockIdx.x * 4;
        for (int i = tid; i < 3072; i += 256) {
            int r = i >> 8, j = i & 255;
            Wsm[r][j] = __ldg(W0h + (size_t)((r % 3) * 256 + u0 + r / 3) * 256 + j);
        }
        int jq = w >> 1, uh = w & 1;
        int ue = u0 + (w & 3);
        float br = __ldg(b0h + ue), bz = __ldg(b0h + 256 + ue), bn = __ldg(b0h + 512 + ue);
        int pidx = (ue >> 1) * 64 + (lane << 1) + (ue & 1);
        const float* wg = Wsm[uh * 6] + (jq << 6);
        int ua = uh * 2, ub = uh * 2 + 1;
        float giR = 0.f, giZ = 0.f, giN = 0.f;
        if (w < 4) {
            giR = d_gi0[0][ue * 32 + lane];
            giZ = d_gi0[0][(256 + ue) * 32 + lane];
            giN = d_gi0[0][(512 + ue) * 32 + lane];
        }
        __syncthreads();
        for (int t = 0; t < 128; t++) {
            const float4* srcp = (const float4*)((t == 0) ? d_h1z : d_h1all[t - 1]);
            float4* dst = (float4*)Hs;
            for (int i = tid; i < 2048; i += 256) dst[i] = __ldcg(srcp + i);
            __syncthreads();
            ull acc[6] = {0, 0, 0, 0, 0, 0};
            gru_dots(Hs + (jq << 11) + (lane << 1), wg, acc);
#pragma unroll
            for (int g = 0; g < 3; g++) {
                parts[ua][g][jq][lane] = fsum(acc[g]);
                parts[ub][g][jq][lane] = fsum(acc[g + 3]);
            }
            __syncthreads();
            if (w < 4) {
                float gR = parts[w][0][0][lane] + parts[w][0][1][lane] +
                           parts[w][0][2][lane] + parts[w][0][3][lane] + br;
                float gZ = parts[w][1][0][lane] + parts[w][1][1][lane] +
                           parts[w][1][2][lane] + parts[w][1][3][lane] + bz;
                float gN = parts[w][2][0][lane] + parts[w][2][1][lane] +
                           parts[w][2][2][lane] + parts[w][2][3][lane] + bn;
                float r = sigm(giR + gR);
                float z = sigm(giZ + gZ);
                float nn = tanhf(giN + r * gN);
                float hN = (1.f - z) * nn + z * Hs[pidx];
                __stcg(&d_h1all[t][pidx], hN);
            }
            __syncthreads();
            if (tid == 0) g_arrive(2);
            if (w < 4 && t < 127) {
                giR = d_gi0[t + 1][ue * 32 + lane];
                giZ = d_gi0[t + 1][(256 + ue) * 32 + lane];
                giN = d_gi0[t + 1][(512 + ue) * 32 + lane];
            }
            if (tid == 0) g_waitge(2, 64u * (t + 1));
            __syncthreads();
        }
    } else {                 // ---------------- GRU1 chain -------------------
        int u0 = (blockIdx.x - 64) * 4;
        for (int i = tid; i < 3072; i += 256) {
            int r = i >> 8, j = i & 255;
            Wsm[r][j] = __ldg(W1i + (size_t)((r % 3) * 256 + u0 + r / 3) * 256 + j);
            Wsm[12 + r][j] = __ldg(W1h + (size_t)((r % 3) * 256 + u0 + r / 3) * 256 + j);
        }
        int mt = w >> 2, jh = (w >> 1) & 1, uh = w & 1;
        int ue = u0 + (w & 3);
        float biR = __ldg(b1i + ue), biZ = __ldg(b1i + 256 + ue), biN = __ldg(b1i + 512 + ue);
        float bhR = __ldg(b1h + ue), bhZ = __ldg(b1h + 256 + ue), bhN = __ldg(b1h + 512 + ue);
        int pidx = (ue >> 1) * 64 + (lane << 1) + (ue & 1);
        int rb = mt * 12 + uh * 6;
        const float* w0 = Wsm[rb + 0] + (jh << 7);
        const float* w1 = Wsm[rb + 1] + (jh << 7);
        const float* w2 = Wsm[rb + 2] + (jh << 7);
        const float* w3 = Wsm[rb + 3] + (jh << 7);
        const float* w4 = Wsm[rb + 4] + (jh << 7);
        const float* w5 = Wsm[rb + 5] + (jh << 7);
        __syncthreads();
        for (int t = 0; t < 128; t++) {
            int par = t & 1;
            {
                const float4* srcp = (const float4*)d_h2p[par];
                float4* dst = (float4*)Hs2;
                for (int i = tid; i < 2048; i += 256) dst[i] = __ldcg(srcp + i);
            }
            __syncthreads();
            if (mt == 0) {
                if (tid == 0) g_waitge(2, 64u * (t + 1));
                asm volatile("bar.sync 1,128;" ::: "memory");
                const float4* srcp = (const float4*)d_h1all[t];
                float4* dst = (float4*)Hs;
                for (int i = tid; i < 2048; i += 128) dst[i] = __ldcg(srcp + i);
                asm volatile("bar.sync 1,128;" ::: "memory");
            }
            ull aA = 0, aB = 0, aC = 0, aD = 0, aE = 0, aF = 0;
            const float* hb = (mt ? Hs2 : Hs) + (jh << 12) + (lane << 1);
#pragma unroll
            for (int it = 0; it < 16; it++) {
                ull h0 = *(const ull*)(hb + (it * 4 + 0) * 64);
                ull h1 = *(const ull*)(hb + (it * 4 + 1) * 64);
                ull h2 = *(const ull*)(hb + (it * 4 + 2) * 64);
                ull h3 = *(const ull*)(hb + (it * 4 + 3) * 64);
                ulonglong2 xa, xb;
                xa = *(const ulonglong2*)(w0 + it * 8); xb = *(const ulonglong2*)(w0 + it * 8 + 4);
                f2(aA, h0, xa.x); f2(aA, h1, xa.y); f2(aA, h2, xb.x); f2(aA, h3, xb.y);
                xa = *(const ulonglong2*)(w1 + it * 8); xb = *(const ulonglong2*)(w1 + it * 8 + 4);
                f2(aB, h0, xa.x); f2(aB, h1, xa.y); f2(aB, h2, xb.x); f2(aB, h3, xb.y);
                xa = *(const ulonglong2*)(w2 + it * 8); xb = *(const ulonglong2*)(w2 + it * 8 + 4);
                f2(aC, h0, xa.x); f2(aC, h1, xa.y); f2(aC, h2, xb.x); f2(aC, h3, xb.y);
                xa = *(const ulonglong2*)(w3 + it * 8); xb = *(const ulonglong2*)(w3 + it * 8 + 4);
                f2(aD, h0, xa.x); f2(aD, h1, xa.y); f2(aD, h2, xb.x); f2(aD, h3, xb.y);
                xa = *(const ulonglong2*)(w4 + it * 8); xb = *(const ulonglong2*)(w4 + it * 8 + 4);
                f2(aE, h0, xa.x); f2(aE, h1, xa.y); f2(aE, h2, xb.x); f2(aE, h3, xb.y);
                xa = *(const ulonglong2*)(w5 + it * 8); xb = *(const ulonglong2*)(w5 + it * 8 + 4);
                f2(aF, h0, xa.x); f2(aF, h1, xa.y); f2(aF, h2, xb.x); f2(aF, h3, xb.y);
            }
            int ua = uh * 2, ub = uh * 2 + 1, col = mt * 2 + jh;
            parts[ua][0][col][lane] = fsum(aA);
            parts[ua][1][col][lane] = fsum(aB);
            parts[ua][2][col][lane] = fsum(aC);
            parts[ub][0][col][lane] = fsum(aD);
            parts[ub][1][col][lane] = fsum(aE);
            parts[ub][2][col][lane] = fsum(aF);
            __syncthreads();
            float hN = 0.f;
            if (w < 4) {
                float giR_ = parts[w][0][0][lane] + parts[w][0][1][lane] + biR;
                float giZ_ = parts[w][1][0][lane] + parts[w][1][1][lane] + biZ;
                float giN_ = parts[w][2][0][lane] + parts[w][2][1][lane] + biN;
                float ghR = parts[w][0][2][lane] + parts[w][0][3][lane] + bhR;
                float ghZ = parts[w][1][2][lane] + parts[w][1][3][lane] + bhZ;
                float ghN = parts[w][2][2][lane] + parts[w][2][3][lane] + bhN;
                float r = sigm(giR_ + ghR);
                float z = sigm(giZ_ + ghZ);
                float nn = tanhf(giN_ + r * ghN);
                hN = (1.f - z) * nn + z * Hs2[pidx];
                __stcg(&d_h2p[par ^ 1][pidx], hN);
            }
            __syncthreads();
            if (tid == 0) g_arrive(3);
            if (w < 4) d_h2all[t][ue * 32 + lane] = hN;
            if (tid == 0) g_waitge(3, 64u * (t + 1));
            __syncthreads();
        }
    }
}

// ---- output GEMM: M=4096(m=t*32+b) K=256 N=512 ----
__global__ void __launch_bounds__(256) out_gemm(
    const float* __restrict__ outW, const float* __restrict__ outb,
    float* __restrict__ out) {
    __shared__ __align__(16) float As[8][128];
    __shared__ __align__(16) float Bs[8][128];
    int n0 = blockIdx.x << 7, m0 = blockIdx.y << 7;
    int tid = threadIdx.x, tx = tid & 31, ty = tid >> 5;
    int nl = tid & 127, kh = tid >> 7;
    const float* Wr = outW + (size_t)(n0 + nl) * 256;
    const float* h2f = (const float*)d_h2all;
    ull acc2[8][4];
#pragma unroll
    for (int i = 0; i < 8; i++)
#pragma unroll
        for (int j = 0; j < 4; j++) acc2[i][j] = 0ull;

    for (int k0 = 0; k0 < 256; k0 += 8) {
#pragma unroll
        for (int i = 0; i < 4; i++) {
            int e = tid + (i << 8);
            int ml = e & 127, kl = e >> 7;
            int m = m0 + ml;
            As[kl][ml] = h2f[(m >> 5) * 8192 + (k0 + kl) * 32 + (m & 31)];
        }
        float4 bv = __ldg((const float4*)(Wr + k0 + (kh << 2)));
        Bs[(kh << 2) + 0][nl] = bv.x;
        Bs[(kh << 2) + 1][nl] = bv.y;
        Bs[(kh << 2) + 2][nl] = bv.z;
        Bs[(kh << 2) + 3][nl] = bv.w;
        __syncthreads();
#pragma unroll
        for (int k = 0; k < 8; k++) {
            ulonglong2 qa0 = *(const ulonglong2*)&As[k][(ty << 4) + 0];
            ulonglong2 qa1 = *(const ulonglong2*)&As[k][(ty << 4) + 4];
            ulonglong2 qa2 = *(const ulonglong2*)&As[k][(ty << 4) + 8];
            ulonglong2 qa3 = *(const ulonglong2*)&As[k][(ty << 4) + 12];
            float4 bv2 = *(const float4*)&Bs[k][tx << 2];
            ull bsp[4] = {splat(bv2.x), splat(bv2.y), splat(bv2.z), splat(bv2.w)};
            ull am[8] = {qa0.x, qa0.y, qa1.x, qa1.y, qa2.x, qa2.y, qa3.x, qa3.y};
#pragma unroll
            for (int mp = 0; mp < 8; mp++) {
                f2(acc2[mp][0], am[mp], bsp[0]);
                f2(acc2[mp][1], am[mp], bsp[1]);
                f2(acc2[mp][2], am[mp], bsp[2]);
                f2(acc2[mp][3], am[mp], bsp[3]);
            }
        }
        __syncthreads();
    }
#pragma unroll
    for (int n = 0; n < 4; n++) {
        int v = n0 + (tx << 2) + n;
        float bias = __ldg(outb + v);
#pragma unroll
        for (int mp = 0; mp < 8; mp++) {
            float lo, hi;
            upk(acc2[mp][n], lo, hi);
            int m = m0 + (ty << 4) + (mp << 1);
            size_t b0 = (size_t)(m & 31) * 65536 + (m >> 5) * 512;
            size_t b1 = (size_t)((m + 1) & 31) * 65536 + ((m + 1) >> 5) * 512;
            out[b0 + v] = lo + bias;
            out[b1 + v] = hi + bias;
        }
    }
}

extern "C" void kernel_launch(void* const* d_in, const int* in_sizes, int n_in,
                              void* d_out, int out_size) {
    const float* src  = (const float*)d_in[0];
    const int*   tgt  = (const int*)d_in[1];
    const float* eWif = (const float*)d_in[2];
    const float* eWhf = (const float*)d_in[3];
    const float* ebif = (const float*)d_in[4];
    const float* ebhf = (const float*)d_in[5];
    const float* eWib = (const float*)d_in[6];
    const float* eWhb = (const float*)d_in[7];
    const float* ebib = (const float*)d_in[8];
    const float* ebhb = (const float*)d_in[9];
    const float* attW = (const float*)d_in[10];
    const float* emb  = (const float*)d_in[12];
    const float* W0i  = (const float*)d_in[13];
    const float* W0h  = (const float*)d_in[14];
    const float* b0i  = (const float*)d_in[15];
    const float* b0h  = (const float*)d_in[16];
    const float* W1i  = (const float*)d_in[17];
    const float* W1h  = (const float*)d_in[18];
    const float* b1i  = (const float*)d_in[19];
    const float* b1h  = (const float*)d_in[20];
    const float* outW = (const float*)d_in[21];
    const float* outb = (const float*)d_in[22];
    float* out = (float*)d_out;

    init_kernel<<<128, 256>>>();                       // 1
    vg_k<<<512, 256>>>(emb, W0i);                      // 2
    enc_gi_gemm<<<dim3(12, 128), 256>>>(src, eWif, eWib, ebif, ebib);  // 3
    enc_rnn<<<128, 256>>>(eWhf, ebhf, eWhb, ebhb);     // 4
    att_score<<<512, 256>>>(attW);                     // 5
    softmax_k<<<32, 256>>>();                          // 6
    ctx_k<<<512, 256>>>();                             // 7
    cg_k<<<768, 256>>>(W0i, b0i);                      // 8
    gi0_k<<<12288, 256>>>(tgt);                        // 9
    dec_rnn<<<128, 256>>>(W0h, b0h, W1i, b1i, W1h, b1h);  // 10
    out_gemm<<<dim3(4, 32), 256>>>(outW, outb, out);   // 11
}